// round 11
// baseline (speedup 1.0000x reference)
#include <cuda_runtime.h>
#include <cstdint>

#define MAXN 100352

typedef unsigned long long ull;

__device__ float g_y[MAXN * 64];   // x @ w03 + b03
__device__ float g_hx[MAXN * 16];  // x @ w01[3:] + b01
__device__ float g_wcat[5120];     // [0:4096)=blS symmetrized, [4096:5120)=c2aF
__device__ float g_c2aQ[192];      // folded q->c2a, BN2a-scale folded
__device__ float g_c2aC[64];       // folded const->c2a, BN2a scale+shift folded
__device__ float g_c2bF[512];      // c2b, BN2b-scale folded

// Uniform weights on the constant port (off the smem crossbar).
__constant__ float c_w[5120];      // [0:4096)=blS, [4096:5120)=c2a

// ---- packed f32x2 helpers (FFMA2) ----
__device__ __forceinline__ ull pk2(float lo, float hi) {
    ull r; asm("mov.b64 %0,{%1,%2};" : "=l"(r) : "f"(lo), "f"(hi)); return r;
}
__device__ __forceinline__ ull bc2(float v) { return pk2(v, v); }
__device__ __forceinline__ void upk2(ull v, float& lo, float& hi) {
    asm("mov.b64 {%0,%1},%2;" : "=f"(lo), "=f"(hi) : "l"(v));
}
__device__ __forceinline__ ull fma2_(ull a, ull b, ull c) {
    ull d; asm("fma.rn.f32x2 %0,%1,%2,%3;" : "=l"(d) : "l"(a), "l"(b), "l"(c)); return d;
}
__device__ __forceinline__ ull add2_(ull a, ull b) {
    ull d; asm("add.rn.f32x2 %0,%1,%2;" : "=l"(d) : "l"(a), "l"(b)); return d;
}
__device__ __forceinline__ ull mul2_(ull a, ull b) {
    ull d; asm("mul.rn.f32x2 %0,%1,%2;" : "=l"(d) : "l"(a), "l"(b)); return d;
}

// ---------------------------------------------------------------------------
// Prep kernel: data blocks compute y & hx; 17 tail blocks do weight setup.
// ---------------------------------------------------------------------------
__global__ void __launch_bounds__(256) prep_kernel(
    const float* __restrict__ x, const float* __restrict__ w03,
    const float* __restrict__ b03, const float* __restrict__ w01,
    const float* __restrict__ b01,
    const float* __restrict__ blW, const float* __restrict__ c2aw,
    const float* __restrict__ lp2w, const float* __restrict__ lp2b,
    const float* __restrict__ bn2ag, const float* __restrict__ bn2ab,
    const float* __restrict__ bn2am, const float* __restrict__ bn2av,
    const float* __restrict__ c2bw, const float* __restrict__ bn2bg,
    const float* __restrict__ bn2bv,
    int n, int nb_data)
{
    const int tid = threadIdx.x;
    if (blockIdx.x >= nb_data) {
        const int sb = blockIdx.x - nb_data;
        if (sb < 16) {
            const int id = sb * 256 + tid;
            const int o = id & 15;
            const int pr = id >> 4;
            const int jj = pr & 15;
            const int i = pr >> 4;
            float v;
            if (i < jj)       v = blW[o * 256 + i * 16 + jj] + blW[o * 256 + jj * 16 + i];
            else if (i == jj) v = blW[o * 256 + i * 16 + i];
            else              v = 0.f;
            g_wcat[id] = v;
        } else {
            __shared__ float sM[48], s0[16];
            __shared__ float sca[64], sha[64];
            if (tid < 48) {
                const int r = tid >> 4, u = tid & 15;
                sM[tid] = lp2w[r * 64 + u] + lp2w[r * 64 + 16 + u] +
                          lp2w[r * 64 + 32 + u] + lp2w[r * 64 + 48 + u];
            }
            if (tid >= 48 && tid < 64) {
                const int u = tid - 48;
                s0[u] = lp2b[u] + lp2b[16 + u] + lp2b[32 + u] + lp2b[48 + u];
            }
            if (tid >= 64 && tid < 128) {
                const int c = tid - 64;
                float sc = bn2ag[c] * rsqrtf(bn2av[c] + 1e-5f);
                sca[c] = sc;
                sha[c] = bn2ab[c] - bn2am[c] * sc;
            }
            __syncthreads();
            if (tid < 192) {
                const int r = tid >> 6, c = tid & 63;
                float acc = 0.f;
#pragma unroll
                for (int u = 0; u < 16; u++)
                    acc += sM[r * 16 + u] * c2aw[(16 + u) * 64 + c];
                g_c2aQ[r * 64 + c] = acc * sca[c];
            } else {
                const int c = tid - 192;
                float acc = 0.f;
#pragma unroll
                for (int u = 0; u < 16; u++)
                    acc += s0[u] * c2aw[(16 + u) * 64 + c];
                g_c2aC[c] = acc * sca[c] + sha[c];
            }
#pragma unroll
            for (int t = 0; t < 4; t++) {
                const int i = tid + t * 256;
                g_wcat[4096 + i] = c2aw[i] * sca[i & 63];
            }
#pragma unroll
            for (int t = 0; t < 2; t++) {
                const int i = tid + t * 256;
                const int u = i & 7;
                g_c2bF[i] = c2bw[i] * (bn2bg[u] * rsqrtf(bn2bv[u] + 1e-5f));
            }
        }
        return;
    }

    __shared__ float sw[4096];
    __shared__ float sw1[1024];
    __shared__ float sx[32][64];
    for (int i = tid; i < 1024; i += 256)
        ((float4*)sw)[i] = ((const float4*)w03)[i];
    for (int i = tid; i < 256; i += 256)
        ((float4*)sw1)[i] = ((const float4*)(w01 + 48))[i];
    const int base = blockIdx.x * 32;
    {
        const int c4 = tid & 15;
        const int r = tid >> 4;
#pragma unroll
        for (int a = 0; a < 2; a++) {
            const int row = base + r + a * 16;
            float4 v = make_float4(0.f, 0.f, 0.f, 0.f);
            if (row < n) v = ((const float4*)(x + (size_t)row * 64))[c4];
            ((float4*)sx[r + a * 16])[c4] = v;
        }
    }
    __syncthreads();

    {
        const int rq = tid >> 5;
        const int cp = tid & 31;
        const ull bcp = ((const ull*)b03)[cp];
        ull acc0 = bcp, acc1 = bcp, acc2 = bcp, acc3 = bcp;
#pragma unroll 8
        for (int d = 0; d < 64; d++) {
            const ull w2 = ((const ull*)(sw + d * 64))[cp];
            acc0 = fma2_(bc2(sx[rq * 4 + 0][d]), w2, acc0);
            acc1 = fma2_(bc2(sx[rq * 4 + 1][d]), w2, acc1);
            acc2 = fma2_(bc2(sx[rq * 4 + 2][d]), w2, acc2);
            acc3 = fma2_(bc2(sx[rq * 4 + 3][d]), w2, acc3);
        }
        const int r0 = base + rq * 4;
        if (r0 + 0 < n) ((ull*)(g_y + (size_t)(r0 + 0) * 64))[cp] = acc0;
        if (r0 + 1 < n) ((ull*)(g_y + (size_t)(r0 + 1) * 64))[cp] = acc1;
        if (r0 + 2 < n) ((ull*)(g_y + (size_t)(r0 + 2) * 64))[cp] = acc2;
        if (r0 + 3 < n) ((ull*)(g_y + (size_t)(r0 + 3) * 64))[cp] = acc3;
    }
    {
        const int r = tid >> 3;
        const int o8 = tid & 7;
        ull acc = ((const ull*)b01)[o8];
#pragma unroll 8
        for (int d = 0; d < 64; d++)
            acc = fma2_(bc2(sx[r][d]), ((const ull*)(sw1 + d * 16))[o8], acc);
        const int row = base + r;
        if (row < n) ((ull*)(g_hx + (size_t)row * 16))[o8] = acc;
    }
}

// ---------------------------------------------------------------------------
// Main kernel: 256 threads, 32 points/block, two-phase, 3 blocks/SM target.
// Phase 1: per-pair math; tail (c2a..softmax) serialized per slot for regs.
// Phase 2: coalesced epilogue, lane = channel pair, no shuffles.
// ---------------------------------------------------------------------------
__global__ void __launch_bounds__(256, 3) pm_main_kernel(
    const float* __restrict__ p,
    const int* __restrict__ knn,
    const float* __restrict__ w01, const float* __restrict__ blB,
    const float* __restrict__ lp1w, const float* __restrict__ lp1b,
    const float* __restrict__ bnpg, const float* __restrict__ bnpb,
    const float* __restrict__ bnpm, const float* __restrict__ bnpv,
    const float* __restrict__ lp2w, const float* __restrict__ lp2b,
    const float* __restrict__ bn2bg, const float* __restrict__ bn2bb,
    const float* __restrict__ bn2bm, const float* __restrict__ bn2bv,
    const float* __restrict__ c2cw, const float* __restrict__ c2cb,
    float* __restrict__ out, float* __restrict__ xk_out,
    float* __restrict__ knn_out, float* __restrict__ pr_out,
    int n)
{
    __shared__ __align__(16) float s_ws[512 * 8];   // softmax weights per pair
    __shared__ __align__(16) float s_q[512 * 4];    // q vec per pair
    __shared__ int   s_j[512];                      // gather index per pair
    __shared__ __align__(16) float s_c2aQ[192];
    __shared__ __align__(16) float s_c2aC[64];
    __shared__ __align__(16) float s_c2b[512];
    __shared__ __align__(16) float s_c2c[64];
    __shared__ __align__(16) float s_lp2[192], s_lp2b[64];
    __shared__ __align__(16) float s_w01p[48];
    __shared__ __align__(16) float s_blB[16];
    __shared__ __align__(16) float s_lp1f[12], s_lp1c[4];
    __shared__ __align__(16) float s_bn2bt[8], s_c2cb[8];

    const int tid = threadIdx.x;

    // ---- staging (small tables only) ----
    if (tid < 128) ((float4*)s_c2b)[tid] = ((const float4*)g_c2bF)[tid];
    if (tid < 192) { s_c2aQ[tid] = g_c2aQ[tid]; s_lp2[tid] = lp2w[tid]; }
    if (tid < 64) {
        s_c2aC[tid] = g_c2aC[tid];
        s_lp2b[tid] = lp2b[tid];
        s_c2c[tid] = c2cw[tid];
    }
    if (tid < 48) s_w01p[tid] = w01[tid];
    if (tid < 16) s_blB[tid] = blB[tid];
    if (tid < 8) {
        float sc = bn2bg[tid] * rsqrtf(bn2bv[tid] + 1e-5f);
        s_bn2bt[tid] = bn2bb[tid] - bn2bm[tid] * sc;
        s_c2cb[tid] = c2cb[tid];
    }
    if (tid < 3) {
        const int d = tid;
        float sc = bnpg[d] * rsqrtf(bnpv[d] + 1e-5f);
        s_lp1f[0 + d] = lp1w[0 * 3 + d] * sc;
        s_lp1f[4 + d] = lp1w[1 * 3 + d] * sc;
        s_lp1f[8 + d] = lp1w[2 * 3 + d] * sc;
        s_lp1c[d] = (lp1b[d] - bnpm[d]) * sc + bnpb[d];
    }
    __syncthreads();

    // ---- pair setup ----
    const int k = tid & 15;
    const int half = (tid >> 4) & 1;
    const int wrp = tid >> 5;
    const int pt0 = wrp * 4 + half * 2;             // point within block
    const int base = blockIdx.x * 32 + pt0;
    const int nn0 = base, nn1 = base + 1;
    const bool v0 = nn0 < n, v1 = nn1 < n;
    const int nc0 = v0 ? nn0 : (n > 0 ? n - 1 : 0);
    const int nc1 = v1 ? nn1 : (n > 0 ? n - 1 : 0);
    const int j0 = knn[(size_t)nc0 * 16 + k];
    const int j1 = knn[(size_t)nc1 * 16 + k];

    const float pA0 = p[(size_t)j0 * 3 + 0] - p[(size_t)nc0 * 3 + 0];
    const float pA1 = p[(size_t)j0 * 3 + 1] - p[(size_t)nc0 * 3 + 1];
    const float pA2 = p[(size_t)j0 * 3 + 2] - p[(size_t)nc0 * 3 + 2];
    const float pB0 = p[(size_t)j1 * 3 + 0] - p[(size_t)nc1 * 3 + 0];
    const float pB1 = p[(size_t)j1 * 3 + 1] - p[(size_t)nc1 * 3 + 1];
    const float pB2 = p[(size_t)j1 * 3 + 2] - p[(size_t)nc1 * 3 + 2];
    if (v0 && pr_out) {
        pr_out[((size_t)nn0 * 16 + k) * 3 + 0] = pA0;
        pr_out[((size_t)nn0 * 16 + k) * 3 + 1] = pA1;
        pr_out[((size_t)nn0 * 16 + k) * 3 + 2] = pA2;
    }
    if (v1 && pr_out) {
        pr_out[((size_t)nn1 * 16 + k) * 3 + 0] = pB0;
        pr_out[((size_t)nn1 * 16 + k) * 3 + 1] = pB1;
        pr_out[((size_t)nn1 * 16 + k) * 3 + 2] = pB2;
    }
    if (v0 && knn_out) knn_out[(size_t)nn0 * 16 + k] = (float)j0;
    if (v1 && knn_out) knn_out[(size_t)nn1 * 16 + k] = (float)j1;

    // ---- q = relu(BN(pr @ lp1)) (compute early; write to smem; pr can die) ----
    float qa[3], qb[3];
#pragma unroll
    for (int d = 0; d < 3; d++) {
        qa[d] = fmaxf(fmaf(pA0, s_lp1f[d], fmaf(pA1, s_lp1f[4 + d], fmaf(pA2, s_lp1f[8 + d], s_lp1c[d]))), 0.f);
        qb[d] = fmaxf(fmaf(pB0, s_lp1f[d], fmaf(pB1, s_lp1f[4 + d], fmaf(pB2, s_lp1f[8 + d], s_lp1c[d]))), 0.f);
    }
    const int pair0 = pt0 * 16 + k;
    const int pair1 = (pt0 + 1) * 16 + k;
    s_q[pair0 * 4 + 0] = qa[0]; s_q[pair0 * 4 + 1] = qa[1];
    s_q[pair0 * 4 + 2] = qa[2]; s_q[pair0 * 4 + 3] = 0.f;
    s_q[pair1 * 4 + 0] = qb[0]; s_q[pair1 * 4 + 1] = qb[1];
    s_q[pair1 * 4 + 2] = qb[2]; s_q[pair1 * 4 + 3] = 0.f;
    s_j[pair0] = j0;
    s_j[pair1] = j1;

    // ---- h = relu(hx[j] + pr @ w01p) ----
    float h0[16], h1[16];
    {
        const float4* hxa = (const float4*)(g_hx + (size_t)j0 * 16);
        const float4* hxb = (const float4*)(g_hx + (size_t)j1 * 16);
#pragma unroll
        for (int o4 = 0; o4 < 4; o4++) {
            float4 a = hxa[o4], b = hxb[o4];
            float4 w0 = *(const float4*)(s_w01p + o4 * 4);
            float4 w1 = *(const float4*)(s_w01p + 16 + o4 * 4);
            float4 w2 = *(const float4*)(s_w01p + 32 + o4 * 4);
            h0[o4 * 4 + 0] = fmaxf(a.x + pA0 * w0.x + pA1 * w1.x + pA2 * w2.x, 0.f);
            h0[o4 * 4 + 1] = fmaxf(a.y + pA0 * w0.y + pA1 * w1.y + pA2 * w2.y, 0.f);
            h0[o4 * 4 + 2] = fmaxf(a.z + pA0 * w0.z + pA1 * w1.z + pA2 * w2.z, 0.f);
            h0[o4 * 4 + 3] = fmaxf(a.w + pA0 * w0.w + pA1 * w1.w + pA2 * w2.w, 0.f);
            h1[o4 * 4 + 0] = fmaxf(b.x + pB0 * w0.x + pB1 * w1.x + pB2 * w2.x, 0.f);
            h1[o4 * 4 + 1] = fmaxf(b.y + pB0 * w0.y + pB1 * w1.y + pB2 * w2.y, 0.f);
            h1[o4 * 4 + 2] = fmaxf(b.z + pB0 * w0.z + pB1 * w1.z + pB2 * w2.z, 0.f);
            h1[o4 * 4 + 3] = fmaxf(b.w + pB0 * w0.w + pB1 * w1.w + pB2 * w2.w, 0.f);
        }
    }

    // ---- symmetrized bilinear (both slots share LDC weight stream) ----
    ull e0p[8], e1p[8];
    {
        const ull* bB = (const ull*)s_blB;
#pragma unroll
        for (int q = 0; q < 8; q++) { ull b = bB[q]; e0p[q] = b; e1p[q] = b; }
    }
#pragma unroll
    for (int i = 0; i < 16; i++) {
#pragma unroll
        for (int jj = i; jj < 16; jj++) {
            const ull ga2 = bc2(h0[i] * h0[jj]);
            const ull gb2 = bc2(h1[i] * h1[jj]);
            const ulonglong2* wr = (const ulonglong2*)(c_w + (i * 16 + jj) * 16);
            ulonglong2 w0 = wr[0], w1 = wr[1], w2 = wr[2], w3 = wr[3];
            e0p[0] = fma2_(ga2, w0.x, e0p[0]); e1p[0] = fma2_(gb2, w0.x, e1p[0]);
            e0p[1] = fma2_(ga2, w0.y, e0p[1]); e1p[1] = fma2_(gb2, w0.y, e1p[1]);
            e0p[2] = fma2_(ga2, w1.x, e0p[2]); e1p[2] = fma2_(gb2, w1.x, e1p[2]);
            e0p[3] = fma2_(ga2, w1.y, e0p[3]); e1p[3] = fma2_(gb2, w1.y, e1p[3]);
            e0p[4] = fma2_(ga2, w2.x, e0p[4]); e1p[4] = fma2_(gb2, w2.x, e1p[4]);
            e0p[5] = fma2_(ga2, w2.y, e0p[5]); e1p[5] = fma2_(gb2, w2.y, e1p[5]);
            e0p[6] = fma2_(ga2, w3.x, e0p[6]); e1p[6] = fma2_(gb2, w3.x, e1p[6]);
            e0p[7] = fma2_(ga2, w3.y, e0p[7]); e1p[7] = fma2_(gb2, w3.y, e1p[7]);
        }
    }

    // ---- per-slot tail: c2a(+q)+relu+c2b, logits, softmax, store ws ----
#define SLOT_TAIL(EP, QV, PAIR)                                                   \
    do {                                                                          \
        ull hbp[4];                                                               \
        {                                                                         \
            const ull* shb = (const ull*)s_bn2bt;                                 \
            _Pragma("unroll")                                                     \
            for (int m = 0; m < 4; m++) hbp[m] = shb[m];                          \
        }                                                                         \
        _Pragma("unroll")                                                         \
        for (int cb = 0; cb < 4; cb++) {                                          \
            ull ap[8];                                                            \
            {                                                                     \
                const ulonglong2* ccp = (const ulonglong2*)(s_c2aC + cb * 16);    \
                ulonglong2 c0 = ccp[0], c1 = ccp[1], c2 = ccp[2], c3 = ccp[3];    \
                ap[0] = c0.x; ap[1] = c0.y; ap[2] = c1.x; ap[3] = c1.y;           \
                ap[4] = c2.x; ap[5] = c2.y; ap[6] = c3.x; ap[7] = c3.y;           \
            }                                                                     \
            _Pragma("unroll")                                                     \
            for (int q8 = 0; q8 < 8; q8++) {                                      \
                float elo, ehi;                                                   \
                upk2(EP[q8], elo, ehi);                                           \
                _Pragma("unroll")                                                 \
                for (int hh = 0; hh < 2; hh++) {                                  \
                    const ull vv = bc2(hh ? ehi : elo);                           \
                    const ulonglong2* wr = (const ulonglong2*)(c_w + 4096 +       \
                        (2 * q8 + hh) * 64 + cb * 16);                            \
                    ulonglong2 w0 = wr[0], w1 = wr[1], w2 = wr[2], w3 = wr[3];    \
                    ap[0] = fma2_(vv, w0.x, ap[0]); ap[1] = fma2_(vv, w0.y, ap[1]);\
                    ap[2] = fma2_(vv, w1.x, ap[2]); ap[3] = fma2_(vv, w1.y, ap[3]);\
                    ap[4] = fma2_(vv, w2.x, ap[4]); ap[5] = fma2_(vv, w2.y, ap[5]);\
                    ap[6] = fma2_(vv, w3.x, ap[6]); ap[7] = fma2_(vv, w3.y, ap[7]);\
                }                                                                 \
            }                                                                     \
            _Pragma("unroll")                                                     \
            for (int r = 0; r < 3; r++) {                                         \
                const ull vv = bc2(QV[r]);                                        \
                const ulonglong2* wr = (const ulonglong2*)(s_c2aQ + r * 64 + cb * 16);\
                ulonglong2 w0 = wr[0], w1 = wr[1], w2 = wr[2], w3 = wr[3];        \
                ap[0] = fma2_(vv, w0.x, ap[0]); ap[1] = fma2_(vv, w0.y, ap[1]);   \
                ap[2] = fma2_(vv, w1.x, ap[2]); ap[3] = fma2_(vv, w1.y, ap[3]);   \
                ap[4] = fma2_(vv, w2.x, ap[4]); ap[5] = fma2_(vv, w2.y, ap[5]);   \
                ap[6] = fma2_(vv, w3.x, ap[6]); ap[7] = fma2_(vv, w3.y, ap[7]);   \
            }                                                                     \
            _Pragma("unroll")                                                     \
            for (int q = 0; q < 8; q++) {                                         \
                float vlo, vhi;                                                   \
                upk2(ap[q], vlo, vhi);                                            \
                vlo = fmaxf(vlo, 0.f);                                            \
                vhi = fmaxf(vhi, 0.f);                                            \
                const ulonglong2* wb0 = (const ulonglong2*)(s_c2b + (cb * 16 + 2 * q) * 8);\
                const ulonglong2* wb1 = (const ulonglong2*)(s_c2b + (cb * 16 + 2 * q + 1) * 8);\
                ulonglong2 u0 = wb0[0], u1 = wb0[1];                              \
                ulonglong2 u2 = wb1[0], u3 = wb1[1];                              \
                const ull bl = bc2(vlo), bh = bc2(vhi);                           \
                hbp[0] = fma2_(bl, u0.x, hbp[0]); hbp[1] = fma2_(bl, u0.y, hbp[1]);\
                hbp[2] = fma2_(bl, u1.x, hbp[2]); hbp[3] = fma2_(bl, u1.y, hbp[3]);\
                hbp[0] = fma2_(bh, u2.x, hbp[0]); hbp[1] = fma2_(bh, u2.y, hbp[1]);\
                hbp[2] = fma2_(bh, u3.x, hbp[2]); hbp[3] = fma2_(bh, u3.y, hbp[3]);\
            }                                                                     \
        }                                                                         \
        float hbs[8];                                                             \
        _Pragma("unroll")                                                         \
        for (int m = 0; m < 4; m++) upk2(hbp[m], hbs[2 * m], hbs[2 * m + 1]);     \
        _Pragma("unroll")                                                         \
        for (int u = 0; u < 8; u++) hbs[u] = fmaxf(hbs[u], 0.f);                  \
        ull lgp[4];                                                               \
        {                                                                         \
            const ull* cbp = (const ull*)s_c2cb;                                  \
            _Pragma("unroll")                                                     \
            for (int m = 0; m < 4; m++) lgp[m] = cbp[m];                          \
        }                                                                         \
        _Pragma("unroll")                                                         \
        for (int u = 0; u < 8; u++) {                                             \
            const ull hv = bc2(hbs[u]);                                           \
            const ulonglong2* wr = (const ulonglong2*)(s_c2c + u * 8);            \
            ulonglong2 w0 = wr[0], w1 = wr[1];                                    \
            lgp[0] = fma2_(hv, w0.x, lgp[0]); lgp[1] = fma2_(hv, w0.y, lgp[1]);   \
            lgp[2] = fma2_(hv, w1.x, lgp[2]); lgp[3] = fma2_(hv, w1.y, lgp[3]);   \
        }                                                                         \
        float ws[8];                                                              \
        _Pragma("unroll")                                                         \
        for (int m = 0; m < 4; m++) {                                             \
            float l0, l1;                                                         \
            upk2(lgp[m], l0, l1);                                                 \
            ws[2 * m] = __expf(l0);                                               \
            ws[2 * m + 1] = __expf(l1);                                           \
        }                                                                         \
        _Pragma("unroll")                                                         \
        for (int c = 0; c < 8; c++) {                                             \
            float sm = ws[c];                                                     \
            _Pragma("unroll")                                                     \
            for (int d = 8; d > 0; d >>= 1)                                       \
                sm += __shfl_xor_sync(0xffffffffu, sm, d);                        \
            ws[c] = __fdividef(ws[c], sm);                                        \
        }                                                                         \
        ull* wsp = (ull*)s_ws;                                                    \
        _Pragma("unroll")                                                         \
        for (int m = 0; m < 4; m++)                                               \
            wsp[(PAIR) * 4 + m] = pk2(ws[2 * m], ws[2 * m + 1]);                  \
    } while (0)

    SLOT_TAIL(e0p, qa, pair0);
    SLOT_TAIL(e1p, qb, pair1);
#undef SLOT_TAIL

    __syncthreads();

    // ---- phase 2: coalesced epilogue. warp w -> points 4w..4w+3;
    //      lane -> channels (2*lane, 2*lane+1). out accumulated over k. ----
    {
        const int lane = tid & 31;
        const int w = tid >> 5;
        const ull l0 = ((const ull*)s_lp2)[lane];
        const ull l1 = ((const ull*)(s_lp2 + 64))[lane];
        const ull l2 = ((const ull*)(s_lp2 + 128))[lane];
        const ull lb = ((const ull*)s_lp2b)[lane];
        const ull* wsp = (const ull*)s_ws;
        const int m = lane & 3;
#pragma unroll
        for (int pt = w * 4; pt < w * 4 + 4; pt++) {
            const int nn = blockIdx.x * 32 + pt;
            const bool v = nn < n;
            ull acc = 0ull;
#pragma unroll
            for (int kk = 0; kk < 16; kk++) {
                const int pair = pt * 16 + kk;
                const int j = s_j[pair];
                float4 qv = *(const float4*)(s_q + pair * 4);
                const ull wsv = wsp[pair * 4 + m];
                const ull y = ((const ull*)(g_y + (size_t)j * 64))[lane];
                ull pe = fma2_(bc2(qv.x), l0,
                         fma2_(bc2(qv.y), l1,
                         fma2_(bc2(qv.z), l2, lb)));
                ull xv = mul2_(add2_(y, pe), wsv);
                if (v && xk_out)
                    ((ull*)(xk_out + ((size_t)nn * 16 + kk) * 64))[lane] = xv;
                acc = add2_(acc, xv);
            }
            if (v) ((ull*)(out + (size_t)nn * 64))[lane] = acc;
        }
    }
}

// ---------------------------------------------------------------------------
extern "C" void kernel_launch(void* const* d_in, const int* in_sizes, int n_in,
                              void* d_out, int out_size)
{
    const float* p    = (const float*)d_in[0];
    const float* x    = (const float*)d_in[1];
    const int*   knn  = (const int*)d_in[2];
    const float* w01  = (const float*)d_in[3];
    const float* b01  = (const float*)d_in[4];
    const float* blW  = (const float*)d_in[5];
    const float* blB  = (const float*)d_in[6];
    const float* lp1w = (const float*)d_in[7];
    const float* lp1b = (const float*)d_in[8];
    const float* bnpg = (const float*)d_in[9];
    const float* bnpb = (const float*)d_in[10];
    const float* bnpm = (const float*)d_in[11];
    const float* bnpv = (const float*)d_in[12];
    const float* lp2w = (const float*)d_in[13];
    const float* lp2b = (const float*)d_in[14];
    const float* c2aw = (const float*)d_in[15];
    const float* bn2ag = (const float*)d_in[16];
    const float* bn2ab = (const float*)d_in[17];
    const float* bn2am = (const float*)d_in[18];
    const float* bn2av = (const float*)d_in[19];
    const float* c2bw  = (const float*)d_in[20];
    const float* bn2bg = (const float*)d_in[21];
    const float* bn2bb = (const float*)d_in[22];
    const float* bn2bm = (const float*)d_in[23];
    const float* bn2bv = (const float*)d_in[24];
    const float* c2cw  = (const float*)d_in[25];
    const float* c2cb  = (const float*)d_in[26];
    const float* w03   = (const float*)d_in[27];
    const float* b03   = (const float*)d_in[28];

    const int n = in_sizes[0] / 3;
    float* out = (float*)d_out;

    const long long total = (long long)n * 64 + (long long)n * 16 * 64 +
                            (long long)n * 16 + (long long)n * 16 * 3;
    float* xk_out = nullptr;
    float* knn_out = nullptr;
    float* pr_out = nullptr;
    if ((long long)out_size >= total) {
        xk_out  = out + (size_t)n * 64;
        knn_out = xk_out + (size_t)n * 16 * 64;
        pr_out  = knn_out + (size_t)n * 16;
    }

    const int nb_data = (n + 31) / 32;
    prep_kernel<<<nb_data + 17, 256>>>(x, w03, b03, w01, b01,
                                       blW, c2aw, lp2w, lp2b,
                                       bn2ag, bn2ab, bn2am, bn2av,
                                       c2bw, bn2bg, bn2bv, n, nb_data);
    // Stage computed weight tables into __constant__ (single D2D memcpy node).
    float* d_wcat = nullptr; cudaGetSymbolAddress((void**)&d_wcat, g_wcat);
    cudaMemcpyToSymbolAsync(c_w, d_wcat, 5120 * sizeof(float), 0,
                            cudaMemcpyDeviceToDevice, 0);
    pm_main_kernel<<<(n + 31) / 32, 256>>>(p, knn, w01, blB,
                               lp1w, lp1b, bnpg, bnpb, bnpm, bnpv, lp2w, lp2b,
                               bn2bg, bn2bb, bn2bm, bn2bv,
                               c2cw, c2cb,
                               out, xk_out, knn_out, pr_out, n);
}

// round 12
// speedup vs baseline: 2.8779x; 2.8779x over previous
#include <cuda_runtime.h>
#include <cstdint>

#define MAXN 100352

typedef unsigned long long ull;

__device__ float g_y[MAXN * 64];   // x @ w03 + b03
__device__ float g_hx[MAXN * 16];  // x @ w01[3:] + b01
__device__ float g_wcat[5632];     // [0:4096)=blS, [4096:5120)=c2aF, [5120:5632)=c2bF
__device__ float g_c2aQ[192];      // folded q->c2a, BN2a-scale folded
__device__ float g_c2aC[64];       // folded const->c2a, BN2a scale+shift folded

// Uniform weights on the constant port (off the smem crossbar).
__constant__ float c_w[5632];      // [0:4096)=blS, [4096:5120)=c2a, [5120:5632)=c2b

// ---- packed f32x2 helpers (FFMA2) ----
__device__ __forceinline__ ull pk2(float lo, float hi) {
    ull r; asm("mov.b64 %0,{%1,%2};" : "=l"(r) : "f"(lo), "f"(hi)); return r;
}
__device__ __forceinline__ ull bc2(float v) { return pk2(v, v); }
__device__ __forceinline__ void upk2(ull v, float& lo, float& hi) {
    asm("mov.b64 {%0,%1},%2;" : "=f"(lo), "=f"(hi) : "l"(v));
}
__device__ __forceinline__ ull fma2_(ull a, ull b, ull c) {
    ull d; asm("fma.rn.f32x2 %0,%1,%2,%3;" : "=l"(d) : "l"(a), "l"(b), "l"(c)); return d;
}
__device__ __forceinline__ ull add2_(ull a, ull b) {
    ull d; asm("add.rn.f32x2 %0,%1,%2;" : "=l"(d) : "l"(a), "l"(b)); return d;
}
__device__ __forceinline__ ull mul2_(ull a, ull b) {
    ull d; asm("mul.rn.f32x2 %0,%1,%2;" : "=l"(d) : "l"(a), "l"(b)); return d;
}

// ---------------------------------------------------------------------------
// Prep kernel: data blocks compute y & hx; 17 tail blocks do weight setup.
// ---------------------------------------------------------------------------
__global__ void __launch_bounds__(256) prep_kernel(
    const float* __restrict__ x, const float* __restrict__ w03,
    const float* __restrict__ b03, const float* __restrict__ w01,
    const float* __restrict__ b01,
    const float* __restrict__ blW, const float* __restrict__ c2aw,
    const float* __restrict__ lp2w, const float* __restrict__ lp2b,
    const float* __restrict__ bn2ag, const float* __restrict__ bn2ab,
    const float* __restrict__ bn2am, const float* __restrict__ bn2av,
    const float* __restrict__ c2bw, const float* __restrict__ bn2bg,
    const float* __restrict__ bn2bv,
    int n, int nb_data)
{
    const int tid = threadIdx.x;
    if (blockIdx.x >= nb_data) {
        const int sb = blockIdx.x - nb_data;
        if (sb < 16) {
            const int id = sb * 256 + tid;
            const int o = id & 15;
            const int pr = id >> 4;
            const int jj = pr & 15;
            const int i = pr >> 4;
            float v;
            if (i < jj)       v = blW[o * 256 + i * 16 + jj] + blW[o * 256 + jj * 16 + i];
            else if (i == jj) v = blW[o * 256 + i * 16 + i];
            else              v = 0.f;
            g_wcat[id] = v;
        } else {
            __shared__ float sM[48], s0[16];
            __shared__ float sca[64], sha[64];
            if (tid < 48) {
                const int r = tid >> 4, u = tid & 15;
                sM[tid] = lp2w[r * 64 + u] + lp2w[r * 64 + 16 + u] +
                          lp2w[r * 64 + 32 + u] + lp2w[r * 64 + 48 + u];
            }
            if (tid >= 48 && tid < 64) {
                const int u = tid - 48;
                s0[u] = lp2b[u] + lp2b[16 + u] + lp2b[32 + u] + lp2b[48 + u];
            }
            if (tid >= 64 && tid < 128) {
                const int c = tid - 64;
                float sc = bn2ag[c] * rsqrtf(bn2av[c] + 1e-5f);
                sca[c] = sc;
                sha[c] = bn2ab[c] - bn2am[c] * sc;
            }
            __syncthreads();
            if (tid < 192) {
                const int r = tid >> 6, c = tid & 63;
                float acc = 0.f;
#pragma unroll
                for (int u = 0; u < 16; u++)
                    acc += sM[r * 16 + u] * c2aw[(16 + u) * 64 + c];
                g_c2aQ[r * 64 + c] = acc * sca[c];
            } else {
                const int c = tid - 192;
                float acc = 0.f;
#pragma unroll
                for (int u = 0; u < 16; u++)
                    acc += s0[u] * c2aw[(16 + u) * 64 + c];
                g_c2aC[c] = acc * sca[c] + sha[c];
            }
#pragma unroll
            for (int t = 0; t < 4; t++) {
                const int i = tid + t * 256;
                g_wcat[4096 + i] = c2aw[i] * sca[i & 63];
            }
#pragma unroll
            for (int t = 0; t < 2; t++) {
                const int i = tid + t * 256;
                const int u = i & 7;
                g_wcat[5120 + i] = c2bw[i] * (bn2bg[u] * rsqrtf(bn2bv[u] + 1e-5f));
            }
        }
        return;
    }

    __shared__ float sw[4096];
    __shared__ float sw1[1024];
    __shared__ float sx[32][64];
    for (int i = tid; i < 1024; i += 256)
        ((float4*)sw)[i] = ((const float4*)w03)[i];
    for (int i = tid; i < 256; i += 256)
        ((float4*)sw1)[i] = ((const float4*)(w01 + 48))[i];
    const int base = blockIdx.x * 32;
    {
        const int c4 = tid & 15;
        const int r = tid >> 4;
#pragma unroll
        for (int a = 0; a < 2; a++) {
            const int row = base + r + a * 16;
            float4 v = make_float4(0.f, 0.f, 0.f, 0.f);
            if (row < n) v = ((const float4*)(x + (size_t)row * 64))[c4];
            ((float4*)sx[r + a * 16])[c4] = v;
        }
    }
    __syncthreads();

    {
        const int rq = tid >> 5;
        const int cp = tid & 31;
        const ull bcp = ((const ull*)b03)[cp];
        ull acc0 = bcp, acc1 = bcp, acc2 = bcp, acc3 = bcp;
#pragma unroll 8
        for (int d = 0; d < 64; d++) {
            const ull w2 = ((const ull*)(sw + d * 64))[cp];
            acc0 = fma2_(bc2(sx[rq * 4 + 0][d]), w2, acc0);
            acc1 = fma2_(bc2(sx[rq * 4 + 1][d]), w2, acc1);
            acc2 = fma2_(bc2(sx[rq * 4 + 2][d]), w2, acc2);
            acc3 = fma2_(bc2(sx[rq * 4 + 3][d]), w2, acc3);
        }
        const int r0 = base + rq * 4;
        if (r0 + 0 < n) ((ull*)(g_y + (size_t)(r0 + 0) * 64))[cp] = acc0;
        if (r0 + 1 < n) ((ull*)(g_y + (size_t)(r0 + 1) * 64))[cp] = acc1;
        if (r0 + 2 < n) ((ull*)(g_y + (size_t)(r0 + 2) * 64))[cp] = acc2;
        if (r0 + 3 < n) ((ull*)(g_y + (size_t)(r0 + 3) * 64))[cp] = acc3;
    }
    {
        const int r = tid >> 3;
        const int o8 = tid & 7;
        ull acc = ((const ull*)b01)[o8];
#pragma unroll 8
        for (int d = 0; d < 64; d++)
            acc = fma2_(bc2(sx[r][d]), ((const ull*)(sw1 + d * 16))[o8], acc);
        const int row = base + r;
        if (row < n) ((ull*)(g_hx + (size_t)row * 16))[o8] = acc;
    }
}

// ---------------------------------------------------------------------------
// Main kernel: 256 threads, 32 points/block, two-phase (R10 structure).
// Phase 1: per-pair math (blS/c2a/c2b via const port), ws/q/j -> smem.
// Phase 2: coalesced epilogue, lane = channel pair, no shuffles.
// ---------------------------------------------------------------------------
__global__ void __launch_bounds__(256, 2) pm_main_kernel(
    const float* __restrict__ p,
    const int* __restrict__ knn,
    const float* __restrict__ w01, const float* __restrict__ blB,
    const float* __restrict__ lp1w, const float* __restrict__ lp1b,
    const float* __restrict__ bnpg, const float* __restrict__ bnpb,
    const float* __restrict__ bnpm, const float* __restrict__ bnpv,
    const float* __restrict__ lp2w, const float* __restrict__ lp2b,
    const float* __restrict__ bn2bg, const float* __restrict__ bn2bb,
    const float* __restrict__ bn2bm, const float* __restrict__ bn2bv,
    const float* __restrict__ c2cw, const float* __restrict__ c2cb,
    float* __restrict__ out, float* __restrict__ xk_out,
    float* __restrict__ knn_out, float* __restrict__ pr_out,
    int n)
{
    __shared__ __align__(16) float s_ws[512 * 8];   // softmax weights per pair
    __shared__ __align__(16) float s_q[512 * 4];    // q vec per pair
    __shared__ int   s_j[512];                      // gather index per pair
    __shared__ __align__(16) float s_c2aQ[192];
    __shared__ __align__(16) float s_c2aC[64];
    __shared__ __align__(16) float s_c2c[64];
    __shared__ __align__(16) float s_lp2[192], s_lp2b[64];
    __shared__ __align__(16) float s_w01p[48];
    __shared__ __align__(16) float s_blB[16];
    __shared__ __align__(16) float s_lp1f[12], s_lp1c[4];
    __shared__ __align__(16) float s_bn2bt[8], s_c2cb[8];

    const int tid = threadIdx.x;

    // ---- staging (small tables only) ----
    if (tid < 192) { s_c2aQ[tid] = g_c2aQ[tid]; s_lp2[tid] = lp2w[tid]; }
    if (tid < 64) {
        s_c2aC[tid] = g_c2aC[tid];
        s_lp2b[tid] = lp2b[tid];
        s_c2c[tid] = c2cw[tid];
    }
    if (tid < 48) s_w01p[tid] = w01[tid];
    if (tid < 16) s_blB[tid] = blB[tid];
    if (tid < 8) {
        float sc = bn2bg[tid] * rsqrtf(bn2bv[tid] + 1e-5f);
        s_bn2bt[tid] = bn2bb[tid] - bn2bm[tid] * sc;
        s_c2cb[tid] = c2cb[tid];
    }
    if (tid < 3) {
        const int d = tid;
        float sc = bnpg[d] * rsqrtf(bnpv[d] + 1e-5f);
        s_lp1f[0 + d] = lp1w[0 * 3 + d] * sc;
        s_lp1f[4 + d] = lp1w[1 * 3 + d] * sc;
        s_lp1f[8 + d] = lp1w[2 * 3 + d] * sc;
        s_lp1c[d] = (lp1b[d] - bnpm[d]) * sc + bnpb[d];
    }
    __syncthreads();

    // ---- pair setup ----
    const int k = tid & 15;
    const int half = (tid >> 4) & 1;
    const int wrp = tid >> 5;
    const int pt0 = wrp * 4 + half * 2;             // point within block
    const int base = blockIdx.x * 32 + pt0;
    const int nn0 = base, nn1 = base + 1;
    const bool v0 = nn0 < n, v1 = nn1 < n;
    const int nc0 = v0 ? nn0 : (n > 0 ? n - 1 : 0);
    const int nc1 = v1 ? nn1 : (n > 0 ? n - 1 : 0);
    const int j0 = knn[(size_t)nc0 * 16 + k];
    const int j1 = knn[(size_t)nc1 * 16 + k];

    const float pA0 = p[(size_t)j0 * 3 + 0] - p[(size_t)nc0 * 3 + 0];
    const float pA1 = p[(size_t)j0 * 3 + 1] - p[(size_t)nc0 * 3 + 1];
    const float pA2 = p[(size_t)j0 * 3 + 2] - p[(size_t)nc0 * 3 + 2];
    const float pB0 = p[(size_t)j1 * 3 + 0] - p[(size_t)nc1 * 3 + 0];
    const float pB1 = p[(size_t)j1 * 3 + 1] - p[(size_t)nc1 * 3 + 1];
    const float pB2 = p[(size_t)j1 * 3 + 2] - p[(size_t)nc1 * 3 + 2];
    if (v0 && pr_out) {
        pr_out[((size_t)nn0 * 16 + k) * 3 + 0] = pA0;
        pr_out[((size_t)nn0 * 16 + k) * 3 + 1] = pA1;
        pr_out[((size_t)nn0 * 16 + k) * 3 + 2] = pA2;
    }
    if (v1 && pr_out) {
        pr_out[((size_t)nn1 * 16 + k) * 3 + 0] = pB0;
        pr_out[((size_t)nn1 * 16 + k) * 3 + 1] = pB1;
        pr_out[((size_t)nn1 * 16 + k) * 3 + 2] = pB2;
    }
    if (v0 && knn_out) knn_out[(size_t)nn0 * 16 + k] = (float)j0;
    if (v1 && knn_out) knn_out[(size_t)nn1 * 16 + k] = (float)j1;

    // ---- h = relu(hx[j] + pr @ w01p) ----
    float h0[16], h1[16];
    {
        const float4* hxa = (const float4*)(g_hx + (size_t)j0 * 16);
        const float4* hxb = (const float4*)(g_hx + (size_t)j1 * 16);
#pragma unroll
        for (int o4 = 0; o4 < 4; o4++) {
            float4 a = hxa[o4], b = hxb[o4];
            float4 w0 = *(const float4*)(s_w01p + o4 * 4);
            float4 w1 = *(const float4*)(s_w01p + 16 + o4 * 4);
            float4 w2 = *(const float4*)(s_w01p + 32 + o4 * 4);
            h0[o4 * 4 + 0] = fmaxf(a.x + pA0 * w0.x + pA1 * w1.x + pA2 * w2.x, 0.f);
            h0[o4 * 4 + 1] = fmaxf(a.y + pA0 * w0.y + pA1 * w1.y + pA2 * w2.y, 0.f);
            h0[o4 * 4 + 2] = fmaxf(a.z + pA0 * w0.z + pA1 * w1.z + pA2 * w2.z, 0.f);
            h0[o4 * 4 + 3] = fmaxf(a.w + pA0 * w0.w + pA1 * w1.w + pA2 * w2.w, 0.f);
            h1[o4 * 4 + 0] = fmaxf(b.x + pB0 * w0.x + pB1 * w1.x + pB2 * w2.x, 0.f);
            h1[o4 * 4 + 1] = fmaxf(b.y + pB0 * w0.y + pB1 * w1.y + pB2 * w2.y, 0.f);
            h1[o4 * 4 + 2] = fmaxf(b.z + pB0 * w0.z + pB1 * w1.z + pB2 * w2.z, 0.f);
            h1[o4 * 4 + 3] = fmaxf(b.w + pB0 * w0.w + pB1 * w1.w + pB2 * w2.w, 0.f);
        }
    }

    // ---- symmetrized bilinear, weights from __constant__ ----
    ull e0p[8], e1p[8];
    {
        const ull* bB = (const ull*)s_blB;
#pragma unroll
        for (int q = 0; q < 8; q++) { ull b = bB[q]; e0p[q] = b; e1p[q] = b; }
    }
#pragma unroll
    for (int i = 0; i < 16; i++) {
#pragma unroll
        for (int jj = i; jj < 16; jj++) {
            const ull ga2 = bc2(h0[i] * h0[jj]);
            const ull gb2 = bc2(h1[i] * h1[jj]);
            const ulonglong2* wr = (const ulonglong2*)(c_w + (i * 16 + jj) * 16);
            ulonglong2 w0 = wr[0], w1 = wr[1], w2 = wr[2], w3 = wr[3];
            e0p[0] = fma2_(ga2, w0.x, e0p[0]); e1p[0] = fma2_(gb2, w0.x, e1p[0]);
            e0p[1] = fma2_(ga2, w0.y, e0p[1]); e1p[1] = fma2_(gb2, w0.y, e1p[1]);
            e0p[2] = fma2_(ga2, w1.x, e0p[2]); e1p[2] = fma2_(gb2, w1.x, e1p[2]);
            e0p[3] = fma2_(ga2, w1.y, e0p[3]); e1p[3] = fma2_(gb2, w1.y, e1p[3]);
            e0p[4] = fma2_(ga2, w2.x, e0p[4]); e1p[4] = fma2_(gb2, w2.x, e1p[4]);
            e0p[5] = fma2_(ga2, w2.y, e0p[5]); e1p[5] = fma2_(gb2, w2.y, e1p[5]);
            e0p[6] = fma2_(ga2, w3.x, e0p[6]); e1p[6] = fma2_(gb2, w3.x, e1p[6]);
            e0p[7] = fma2_(ga2, w3.y, e0p[7]); e1p[7] = fma2_(gb2, w3.y, e1p[7]);
        }
    }

    // ---- q vec ----
    float qa[3], qb[3];
#pragma unroll
    for (int d = 0; d < 3; d++) {
        qa[d] = fmaxf(fmaf(pA0, s_lp1f[d], fmaf(pA1, s_lp1f[4 + d], fmaf(pA2, s_lp1f[8 + d], s_lp1c[d]))), 0.f);
        qb[d] = fmaxf(fmaf(pB0, s_lp1f[d], fmaf(pB1, s_lp1f[4 + d], fmaf(pB2, s_lp1f[8 + d], s_lp1c[d]))), 0.f);
    }

    // ---- fused c2a(+q, BN folded)+relu+c2b(BN-scale folded, const) ----
    ull hb0p[4], hb1p[4];
    {
        const ull* shb = (const ull*)s_bn2bt;
#pragma unroll
        for (int m = 0; m < 4; m++) { ull b = shb[m]; hb0p[m] = b; hb1p[m] = b; }
    }
#pragma unroll
    for (int cb = 0; cb < 4; cb++) {
        ull a0p[8], a1p[8];
        {
            const ulonglong2* ccp = (const ulonglong2*)(s_c2aC + cb * 16);
            ulonglong2 c0 = ccp[0], c1 = ccp[1], c2 = ccp[2], c3 = ccp[3];
            a0p[0] = c0.x; a0p[1] = c0.y; a0p[2] = c1.x; a0p[3] = c1.y;
            a0p[4] = c2.x; a0p[5] = c2.y; a0p[6] = c3.x; a0p[7] = c3.y;
#pragma unroll
            for (int q = 0; q < 8; q++) a1p[q] = a0p[q];
        }
#pragma unroll
        for (int q8 = 0; q8 < 8; q8++) {
            float e0lo, e0hi, e1lo, e1hi;
            upk2(e0p[q8], e0lo, e0hi);
            upk2(e1p[q8], e1lo, e1hi);
#pragma unroll
            for (int hh = 0; hh < 2; hh++) {
                const ull va2 = bc2(hh ? e0hi : e0lo);
                const ull vb2 = bc2(hh ? e1hi : e1lo);
                const ulonglong2* wr = (const ulonglong2*)(c_w + 4096 + (2 * q8 + hh) * 64 + cb * 16);
                ulonglong2 w0 = wr[0], w1 = wr[1], w2 = wr[2], w3 = wr[3];
                a0p[0] = fma2_(va2, w0.x, a0p[0]); a1p[0] = fma2_(vb2, w0.x, a1p[0]);
                a0p[1] = fma2_(va2, w0.y, a0p[1]); a1p[1] = fma2_(vb2, w0.y, a1p[1]);
                a0p[2] = fma2_(va2, w1.x, a0p[2]); a1p[2] = fma2_(vb2, w1.x, a1p[2]);
                a0p[3] = fma2_(va2, w1.y, a0p[3]); a1p[3] = fma2_(vb2, w1.y, a1p[3]);
                a0p[4] = fma2_(va2, w2.x, a0p[4]); a1p[4] = fma2_(vb2, w2.x, a1p[4]);
                a0p[5] = fma2_(va2, w2.y, a0p[5]); a1p[5] = fma2_(vb2, w2.y, a1p[5]);
                a0p[6] = fma2_(va2, w3.x, a0p[6]); a1p[6] = fma2_(vb2, w3.x, a1p[6]);
                a0p[7] = fma2_(va2, w3.y, a0p[7]); a1p[7] = fma2_(vb2, w3.y, a1p[7]);
            }
        }
#pragma unroll
        for (int r = 0; r < 3; r++) {
            const ull va2 = bc2(qa[r]);
            const ull vb2 = bc2(qb[r]);
            const ulonglong2* wr = (const ulonglong2*)(s_c2aQ + r * 64 + cb * 16);
            ulonglong2 w0 = wr[0], w1 = wr[1], w2 = wr[2], w3 = wr[3];
            a0p[0] = fma2_(va2, w0.x, a0p[0]); a1p[0] = fma2_(vb2, w0.x, a1p[0]);
            a0p[1] = fma2_(va2, w0.y, a0p[1]); a1p[1] = fma2_(vb2, w0.y, a1p[1]);
            a0p[2] = fma2_(va2, w1.x, a0p[2]); a1p[2] = fma2_(vb2, w1.x, a1p[2]);
            a0p[3] = fma2_(va2, w1.y, a0p[3]); a1p[3] = fma2_(vb2, w1.y, a1p[3]);
            a0p[4] = fma2_(va2, w2.x, a0p[4]); a1p[4] = fma2_(vb2, w2.x, a1p[4]);
            a0p[5] = fma2_(va2, w2.y, a0p[5]); a1p[5] = fma2_(vb2, w2.y, a1p[5]);
            a0p[6] = fma2_(va2, w3.x, a0p[6]); a1p[6] = fma2_(vb2, w3.x, a1p[6]);
            a0p[7] = fma2_(va2, w3.y, a0p[7]); a1p[7] = fma2_(vb2, w3.y, a1p[7]);
        }
        // relu (BN folded) + c2b (scale folded, from const)
#pragma unroll
        for (int q = 0; q < 8; q++) {
            float v00, v01, v10, v11;
            upk2(a0p[q], v00, v01); upk2(a1p[q], v10, v11);
            v00 = fmaxf(v00, 0.f);
            v01 = fmaxf(v01, 0.f);
            v10 = fmaxf(v10, 0.f);
            v11 = fmaxf(v11, 0.f);
            const ulonglong2* wb0 = (const ulonglong2*)(c_w + 5120 + (cb * 16 + 2 * q) * 8);
            const ulonglong2* wb1 = (const ulonglong2*)(c_w + 5120 + (cb * 16 + 2 * q + 1) * 8);
            ulonglong2 u0 = wb0[0], u1 = wb0[1];
            ulonglong2 u2 = wb1[0], u3 = wb1[1];
            const ull va2 = bc2(v00), vA2 = bc2(v01);
            const ull vb2 = bc2(v10), vB2 = bc2(v11);
            hb0p[0] = fma2_(va2, u0.x, hb0p[0]); hb0p[1] = fma2_(va2, u0.y, hb0p[1]);
            hb0p[2] = fma2_(va2, u1.x, hb0p[2]); hb0p[3] = fma2_(va2, u1.y, hb0p[3]);
            hb0p[0] = fma2_(vA2, u2.x, hb0p[0]); hb0p[1] = fma2_(vA2, u2.y, hb0p[1]);
            hb0p[2] = fma2_(vA2, u3.x, hb0p[2]); hb0p[3] = fma2_(vA2, u3.y, hb0p[3]);
            hb1p[0] = fma2_(vb2, u0.x, hb1p[0]); hb1p[1] = fma2_(vb2, u0.y, hb1p[1]);
            hb1p[2] = fma2_(vb2, u1.x, hb1p[2]); hb1p[3] = fma2_(vb2, u1.y, hb1p[3]);
            hb1p[0] = fma2_(vB2, u2.x, hb1p[0]); hb1p[1] = fma2_(vB2, u2.y, hb1p[1]);
            hb1p[2] = fma2_(vB2, u3.x, hb1p[2]); hb1p[3] = fma2_(vB2, u3.y, hb1p[3]);
        }
    }
    float hbs0[8], hbs1[8];
#pragma unroll
    for (int m = 0; m < 4; m++) {
        upk2(hb0p[m], hbs0[2 * m], hbs0[2 * m + 1]);
        upk2(hb1p[m], hbs1[2 * m], hbs1[2 * m + 1]);
    }
#pragma unroll
    for (int u = 0; u < 8; u++) {
        hbs0[u] = fmaxf(hbs0[u], 0.f);
        hbs1[u] = fmaxf(hbs1[u], 0.f);
    }

    // ---- logits (packed) ----
    ull lg0p[4], lg1p[4];
    {
        const ull* cbp = (const ull*)s_c2cb;
#pragma unroll
        for (int m = 0; m < 4; m++) { ull b = cbp[m]; lg0p[m] = b; lg1p[m] = b; }
    }
#pragma unroll
    for (int u = 0; u < 8; u++) {
        const ull h02 = bc2(hbs0[u]);
        const ull h12 = bc2(hbs1[u]);
        const ulonglong2* wr = (const ulonglong2*)(s_c2c + u * 8);
        ulonglong2 w0 = wr[0], w1 = wr[1];
        lg0p[0] = fma2_(h02, w0.x, lg0p[0]); lg1p[0] = fma2_(h12, w0.x, lg1p[0]);
        lg0p[1] = fma2_(h02, w0.y, lg0p[1]); lg1p[1] = fma2_(h12, w0.y, lg1p[1]);
        lg0p[2] = fma2_(h02, w1.x, lg0p[2]); lg1p[2] = fma2_(h12, w1.x, lg1p[2]);
        lg0p[3] = fma2_(h02, w1.y, lg0p[3]); lg1p[3] = fma2_(h12, w1.y, lg1p[3]);
    }

    // ---- softmax over 16 k-lanes (no max pass; |logits| << 1) ----
    float ws0[8], ws1[8];
#pragma unroll
    for (int m = 0; m < 4; m++) {
        float l0, l1;
        upk2(lg0p[m], l0, l1);
        ws0[2 * m] = __expf(l0); ws0[2 * m + 1] = __expf(l1);
        upk2(lg1p[m], l0, l1);
        ws1[2 * m] = __expf(l0); ws1[2 * m + 1] = __expf(l1);
    }
#pragma unroll
    for (int c = 0; c < 8; c++) {
        float s0 = ws0[c], s1 = ws1[c];
#pragma unroll
        for (int d = 8; d > 0; d >>= 1) {
            s0 += __shfl_xor_sync(0xffffffffu, s0, d);
            s1 += __shfl_xor_sync(0xffffffffu, s1, d);
        }
        ws0[c] = __fdividef(ws0[c], s0);
        ws1[c] = __fdividef(ws1[c], s1);
    }

    // ---- write per-pair state to smem for coalesced phase 2 ----
    {
        const int pair0 = pt0 * 16 + k;
        const int pair1 = (pt0 + 1) * 16 + k;
        ull* wsp = (ull*)s_ws;
#pragma unroll
        for (int m = 0; m < 4; m++) {
            wsp[pair0 * 4 + m] = pk2(ws0[2 * m], ws0[2 * m + 1]);
            wsp[pair1 * 4 + m] = pk2(ws1[2 * m], ws1[2 * m + 1]);
        }
        s_q[pair0 * 4 + 0] = qa[0]; s_q[pair0 * 4 + 1] = qa[1];
        s_q[pair0 * 4 + 2] = qa[2]; s_q[pair0 * 4 + 3] = 0.f;
        s_q[pair1 * 4 + 0] = qb[0]; s_q[pair1 * 4 + 1] = qb[1];
        s_q[pair1 * 4 + 2] = qb[2]; s_q[pair1 * 4 + 3] = 0.f;
        s_j[pair0] = j0;
        s_j[pair1] = j1;
    }
    __syncthreads();

    // ---- phase 2: coalesced epilogue. warp w -> points 4w..4w+3;
    //      lane -> channels (2*lane, 2*lane+1). out accumulated over k. ----
    {
        const int lane = tid & 31;
        const int w = tid >> 5;
        const ull l0 = ((const ull*)s_lp2)[lane];
        const ull l1 = ((const ull*)(s_lp2 + 64))[lane];
        const ull l2 = ((const ull*)(s_lp2 + 128))[lane];
        const ull lb = ((const ull*)s_lp2b)[lane];
        const ull* wsp = (const ull*)s_ws;
        const int m = lane & 3;
#pragma unroll
        for (int pt = w * 4; pt < w * 4 + 4; pt++) {
            const int nn = blockIdx.x * 32 + pt;
            const bool v = nn < n;
            ull acc = 0ull;
#pragma unroll
            for (int kk = 0; kk < 16; kk++) {
                const int pair = pt * 16 + kk;
                const int j = s_j[pair];
                float4 qv = *(const float4*)(s_q + pair * 4);
                const ull wsv = wsp[pair * 4 + m];
                const ull y = ((const ull*)(g_y + (size_t)j * 64))[lane];
                ull pe = fma2_(bc2(qv.x), l0,
                         fma2_(bc2(qv.y), l1,
                         fma2_(bc2(qv.z), l2, lb)));
                ull xv = mul2_(add2_(y, pe), wsv);
                if (v && xk_out)
                    ((ull*)(xk_out + ((size_t)nn * 16 + kk) * 64))[lane] = xv;
                acc = add2_(acc, xv);
            }
            if (v) ((ull*)(out + (size_t)nn * 64))[lane] = acc;
        }
    }
}

// ---------------------------------------------------------------------------
extern "C" void kernel_launch(void* const* d_in, const int* in_sizes, int n_in,
                              void* d_out, int out_size)
{
    const float* p    = (const float*)d_in[0];
    const float* x    = (const float*)d_in[1];
    const int*   knn  = (const int*)d_in[2];
    const float* w01  = (const float*)d_in[3];
    const float* b01  = (const float*)d_in[4];
    const float* blW  = (const float*)d_in[5];
    const float* blB  = (const float*)d_in[6];
    const float* lp1w = (const float*)d_in[7];
    const float* lp1b = (const float*)d_in[8];
    const float* bnpg = (const float*)d_in[9];
    const float* bnpb = (const float*)d_in[10];
    const float* bnpm = (const float*)d_in[11];
    const float* bnpv = (const float*)d_in[12];
    const float* lp2w = (const float*)d_in[13];
    const float* lp2b = (const float*)d_in[14];
    const float* c2aw = (const float*)d_in[15];
    const float* bn2ag = (const float*)d_in[16];
    const float* bn2ab = (const float*)d_in[17];
    const float* bn2am = (const float*)d_in[18];
    const float* bn2av = (const float*)d_in[19];
    const float* c2bw  = (const float*)d_in[20];
    const float* bn2bg = (const float*)d_in[21];
    const float* bn2bb = (const float*)d_in[22];
    const float* bn2bm = (const float*)d_in[23];
    const float* bn2bv = (const float*)d_in[24];
    const float* c2cw  = (const float*)d_in[25];
    const float* c2cb  = (const float*)d_in[26];
    const float* w03   = (const float*)d_in[27];
    const float* b03   = (const float*)d_in[28];

    const int n = in_sizes[0] / 3;
    float* out = (float*)d_out;

    const long long total = (long long)n * 64 + (long long)n * 16 * 64 +
                            (long long)n * 16 + (long long)n * 16 * 3;
    float* xk_out = nullptr;
    float* knn_out = nullptr;
    float* pr_out = nullptr;
    if ((long long)out_size >= total) {
        xk_out  = out + (size_t)n * 64;
        knn_out = xk_out + (size_t)n * 16 * 64;
        pr_out  = knn_out + (size_t)n * 16;
    }

    const int nb_data = (n + 31) / 32;
    prep_kernel<<<nb_data + 17, 256>>>(x, w03, b03, w01, b01,
                                       blW, c2aw, lp2w, lp2b,
                                       bn2ag, bn2ab, bn2am, bn2av,
                                       c2bw, bn2bg, bn2bv, n, nb_data);
    // Stage computed weight tables into __constant__ (single D2D memcpy node).
    float* d_wcat = nullptr; cudaGetSymbolAddress((void**)&d_wcat, g_wcat);
    cudaMemcpyToSymbolAsync(c_w, d_wcat, 5632 * sizeof(float), 0,
                            cudaMemcpyDeviceToDevice, 0);
    pm_main_kernel<<<(n + 31) / 32, 256>>>(p, knn, w01, blB,
                               lp1w, lp1b, bnpg, bnpb, bnpm, bnpv, lp2w, lp2b,
                               bn2bg, bn2bb, bn2bm, bn2bv,
                               c2cw, c2cb,
                               out, xk_out, knn_out, pr_out, n);
}

// round 13
// speedup vs baseline: 2.9522x; 1.0258x over previous
#include <cuda_runtime.h>
#include <cstdint>

#define MAXN 100352

typedef unsigned long long ull;

__device__ float g_y[MAXN * 64];   // x @ w03 + b03
__device__ float g_hx[MAXN * 16];  // x @ w01[3:] + b01
__device__ float g_wcat[5120];     // [0:4096)=blS symmetrized, [4096:5120)=c2aF
__device__ float g_c2aQ[192];      // folded q->c2a, BN2a-scale folded
__device__ float g_c2aC[64];       // folded const->c2a, BN2a scale+shift folded
__device__ float g_c2bF[512];      // c2b, BN2b-scale folded

// Uniform weights on the constant port (off the smem crossbar).
__constant__ float c_w[5120];      // [0:4096)=blS, [4096:5120)=c2a

// ---- packed f32x2 helpers (FFMA2) ----
__device__ __forceinline__ ull pk2(float lo, float hi) {
    ull r; asm("mov.b64 %0,{%1,%2};" : "=l"(r) : "f"(lo), "f"(hi)); return r;
}
__device__ __forceinline__ ull bc2(float v) { return pk2(v, v); }
__device__ __forceinline__ void upk2(ull v, float& lo, float& hi) {
    asm("mov.b64 {%0,%1},%2;" : "=f"(lo), "=f"(hi) : "l"(v));
}
__device__ __forceinline__ ull fma2_(ull a, ull b, ull c) {
    ull d; asm("fma.rn.f32x2 %0,%1,%2,%3;" : "=l"(d) : "l"(a), "l"(b), "l"(c)); return d;
}
__device__ __forceinline__ ull add2_(ull a, ull b) {
    ull d; asm("add.rn.f32x2 %0,%1,%2;" : "=l"(d) : "l"(a), "l"(b)); return d;
}
__device__ __forceinline__ ull mul2_(ull a, ull b) {
    ull d; asm("mul.rn.f32x2 %0,%1,%2;" : "=l"(d) : "l"(a), "l"(b)); return d;
}

// ---------------------------------------------------------------------------
// Prep kernel: data blocks (64 rows each) compute y & hx; 17 tail blocks
// do weight setup.
// ---------------------------------------------------------------------------
__global__ void __launch_bounds__(256) prep_kernel(
    const float* __restrict__ x, const float* __restrict__ w03,
    const float* __restrict__ b03, const float* __restrict__ w01,
    const float* __restrict__ b01,
    const float* __restrict__ blW, const float* __restrict__ c2aw,
    const float* __restrict__ lp2w, const float* __restrict__ lp2b,
    const float* __restrict__ bn2ag, const float* __restrict__ bn2ab,
    const float* __restrict__ bn2am, const float* __restrict__ bn2av,
    const float* __restrict__ c2bw, const float* __restrict__ bn2bg,
    const float* __restrict__ bn2bv,
    int n, int nb_data)
{
    const int tid = threadIdx.x;
    if (blockIdx.x >= nb_data) {
        const int sb = blockIdx.x - nb_data;
        if (sb < 16) {
            const int id = sb * 256 + tid;
            const int o = id & 15;
            const int pr = id >> 4;
            const int jj = pr & 15;
            const int i = pr >> 4;
            float v;
            if (i < jj)       v = blW[o * 256 + i * 16 + jj] + blW[o * 256 + jj * 16 + i];
            else if (i == jj) v = blW[o * 256 + i * 16 + i];
            else              v = 0.f;
            g_wcat[id] = v;
        } else {
            __shared__ float sM[48], s0[16];
            __shared__ float sca[64], sha[64];
            if (tid < 48) {
                const int r = tid >> 4, u = tid & 15;
                sM[tid] = lp2w[r * 64 + u] + lp2w[r * 64 + 16 + u] +
                          lp2w[r * 64 + 32 + u] + lp2w[r * 64 + 48 + u];
            }
            if (tid >= 48 && tid < 64) {
                const int u = tid - 48;
                s0[u] = lp2b[u] + lp2b[16 + u] + lp2b[32 + u] + lp2b[48 + u];
            }
            if (tid >= 64 && tid < 128) {
                const int c = tid - 64;
                float sc = bn2ag[c] * rsqrtf(bn2av[c] + 1e-5f);
                sca[c] = sc;
                sha[c] = bn2ab[c] - bn2am[c] * sc;
            }
            __syncthreads();
            if (tid < 192) {
                const int r = tid >> 6, c = tid & 63;
                float acc = 0.f;
#pragma unroll
                for (int u = 0; u < 16; u++)
                    acc += sM[r * 16 + u] * c2aw[(16 + u) * 64 + c];
                g_c2aQ[r * 64 + c] = acc * sca[c];
            } else {
                const int c = tid - 192;
                float acc = 0.f;
#pragma unroll
                for (int u = 0; u < 16; u++)
                    acc += s0[u] * c2aw[(16 + u) * 64 + c];
                g_c2aC[c] = acc * sca[c] + sha[c];
            }
#pragma unroll
            for (int t = 0; t < 4; t++) {
                const int i = tid + t * 256;
                g_wcat[4096 + i] = c2aw[i] * sca[i & 63];
            }
#pragma unroll
            for (int t = 0; t < 2; t++) {
                const int i = tid + t * 256;
                const int u = i & 7;
                g_c2bF[i] = c2bw[i] * (bn2bg[u] * rsqrtf(bn2bv[u] + 1e-5f));
            }
        }
        return;
    }

    __shared__ float sw[4096];
    __shared__ float sw1[1024];
    __shared__ float sx[64][64];
    for (int i = tid; i < 1024; i += 256)
        ((float4*)sw)[i] = ((const float4*)w03)[i];
    for (int i = tid; i < 256; i += 256)
        ((float4*)sw1)[i] = ((const float4*)(w01 + 48))[i];
    const int base = blockIdx.x * 64;
    {
        const int c4 = tid & 15;
        const int r = tid >> 4;
#pragma unroll
        for (int a = 0; a < 4; a++) {
            const int row = base + r + a * 16;
            float4 v = make_float4(0.f, 0.f, 0.f, 0.f);
            if (row < n) v = ((const float4*)(x + (size_t)row * 64))[c4];
            ((float4*)sx[r + a * 16])[c4] = v;
        }
    }
    __syncthreads();

    // y: warp rq handles rows rq*8..rq*8+7; lane cp -> channels 2cp,2cp+1
    {
        const int rq = tid >> 5;
        const int cp = tid & 31;
        const ull bcp = ((const ull*)b03)[cp];
        ull acc[8];
#pragma unroll
        for (int s = 0; s < 8; s++) acc[s] = bcp;
#pragma unroll 8
        for (int d = 0; d < 64; d++) {
            const ull w2 = ((const ull*)(sw + d * 64))[cp];
#pragma unroll
            for (int s = 0; s < 8; s++)
                acc[s] = fma2_(bc2(sx[rq * 8 + s][d]), w2, acc[s]);
        }
        const int r0 = base + rq * 8;
#pragma unroll
        for (int s = 0; s < 8; s++)
            if (r0 + s < n) ((ull*)(g_y + (size_t)(r0 + s) * 64))[cp] = acc[s];
    }
    // hx: thread covers 2 rows (tid>>3 and +32); lane o8 -> channels 2o8,2o8+1
    {
        const int o8 = tid & 7;
#pragma unroll
        for (int a = 0; a < 2; a++) {
            const int r = (tid >> 3) + a * 32;
            ull acc = ((const ull*)b01)[o8];
#pragma unroll 8
            for (int d = 0; d < 64; d++)
                acc = fma2_(bc2(sx[r][d]), ((const ull*)(sw1 + d * 16))[o8], acc);
            const int row = base + r;
            if (row < n) ((ull*)(g_hx + (size_t)row * 16))[o8] = acc;
        }
    }
}

// ---------------------------------------------------------------------------
// Main kernel: 256 threads, 32 points/block, two-phase (R10 structure).
// Phase 1: per-pair math (blS/c2a via const port, c2b via smem), ws/q/j -> smem.
// Phase 2: coalesced epilogue, lane = channel pair, no shuffles.
// ---------------------------------------------------------------------------
__global__ void __launch_bounds__(256, 2) pm_main_kernel(
    const float* __restrict__ p,
    const int* __restrict__ knn,
    const float* __restrict__ w01, const float* __restrict__ blB,
    const float* __restrict__ lp1w, const float* __restrict__ lp1b,
    const float* __restrict__ bnpg, const float* __restrict__ bnpb,
    const float* __restrict__ bnpm, const float* __restrict__ bnpv,
    const float* __restrict__ lp2w, const float* __restrict__ lp2b,
    const float* __restrict__ bn2bg, const float* __restrict__ bn2bb,
    const float* __restrict__ bn2bm, const float* __restrict__ bn2bv,
    const float* __restrict__ c2cw, const float* __restrict__ c2cb,
    float* __restrict__ out, float* __restrict__ xk_out,
    float* __restrict__ knn_out, float* __restrict__ pr_out,
    int n)
{
    __shared__ __align__(16) float s_ws[512 * 8];   // softmax weights per pair
    __shared__ __align__(16) float s_q[512 * 4];    // q vec per pair
    __shared__ int   s_j[512];                      // gather index per pair
    __shared__ __align__(16) float s_c2aQ[192];
    __shared__ __align__(16) float s_c2aC[64];
    __shared__ __align__(16) float s_c2b[512];
    __shared__ __align__(16) float s_c2c[64];
    __shared__ __align__(16) float s_lp2[192], s_lp2b[64];
    __shared__ __align__(16) float s_w01p[48];
    __shared__ __align__(16) float s_blB[16];
    __shared__ __align__(16) float s_lp1f[12], s_lp1c[4];
    __shared__ __align__(16) float s_bn2bt[8], s_c2cb[8];

    const int tid = threadIdx.x;

    // ---- staging (small tables only) ----
    if (tid < 128) ((float4*)s_c2b)[tid] = ((const float4*)g_c2bF)[tid];
    if (tid < 192) { s_c2aQ[tid] = g_c2aQ[tid]; s_lp2[tid] = lp2w[tid]; }
    if (tid < 64) {
        s_c2aC[tid] = g_c2aC[tid];
        s_lp2b[tid] = lp2b[tid];
        s_c2c[tid] = c2cw[tid];
    }
    if (tid < 48) s_w01p[tid] = w01[tid];
    if (tid < 16) s_blB[tid] = blB[tid];
    if (tid < 8) {
        float sc = bn2bg[tid] * rsqrtf(bn2bv[tid] + 1e-5f);
        s_bn2bt[tid] = bn2bb[tid] - bn2bm[tid] * sc;
        s_c2cb[tid] = c2cb[tid];
    }
    if (tid < 3) {
        const int d = tid;
        float sc = bnpg[d] * rsqrtf(bnpv[d] + 1e-5f);
        s_lp1f[0 + d] = lp1w[0 * 3 + d] * sc;
        s_lp1f[4 + d] = lp1w[1 * 3 + d] * sc;
        s_lp1f[8 + d] = lp1w[2 * 3 + d] * sc;
        s_lp1c[d] = (lp1b[d] - bnpm[d]) * sc + bnpb[d];
    }
    __syncthreads();

    // ---- pair setup ----
    const int k = tid & 15;
    const int half = (tid >> 4) & 1;
    const int wrp = tid >> 5;
    const int pt0 = wrp * 4 + half * 2;             // point within block
    const int base = blockIdx.x * 32 + pt0;
    const int nn0 = base, nn1 = base + 1;
    const bool v0 = nn0 < n, v1 = nn1 < n;
    const int nc0 = v0 ? nn0 : (n > 0 ? n - 1 : 0);
    const int nc1 = v1 ? nn1 : (n > 0 ? n - 1 : 0);
    const int j0 = knn[(size_t)nc0 * 16 + k];
    const int j1 = knn[(size_t)nc1 * 16 + k];

    const float pA0 = p[(size_t)j0 * 3 + 0] - p[(size_t)nc0 * 3 + 0];
    const float pA1 = p[(size_t)j0 * 3 + 1] - p[(size_t)nc0 * 3 + 1];
    const float pA2 = p[(size_t)j0 * 3 + 2] - p[(size_t)nc0 * 3 + 2];
    const float pB0 = p[(size_t)j1 * 3 + 0] - p[(size_t)nc1 * 3 + 0];
    const float pB1 = p[(size_t)j1 * 3 + 1] - p[(size_t)nc1 * 3 + 1];
    const float pB2 = p[(size_t)j1 * 3 + 2] - p[(size_t)nc1 * 3 + 2];
    if (v0 && pr_out) {
        pr_out[((size_t)nn0 * 16 + k) * 3 + 0] = pA0;
        pr_out[((size_t)nn0 * 16 + k) * 3 + 1] = pA1;
        pr_out[((size_t)nn0 * 16 + k) * 3 + 2] = pA2;
    }
    if (v1 && pr_out) {
        pr_out[((size_t)nn1 * 16 + k) * 3 + 0] = pB0;
        pr_out[((size_t)nn1 * 16 + k) * 3 + 1] = pB1;
        pr_out[((size_t)nn1 * 16 + k) * 3 + 2] = pB2;
    }
    if (v0 && knn_out) knn_out[(size_t)nn0 * 16 + k] = (float)j0;
    if (v1 && knn_out) knn_out[(size_t)nn1 * 16 + k] = (float)j1;

    // ---- h = relu(hx[j] + pr @ w01p) ----
    float h0[16], h1[16];
    {
        const float4* hxa = (const float4*)(g_hx + (size_t)j0 * 16);
        const float4* hxb = (const float4*)(g_hx + (size_t)j1 * 16);
#pragma unroll
        for (int o4 = 0; o4 < 4; o4++) {
            float4 a = hxa[o4], b = hxb[o4];
            float4 w0 = *(const float4*)(s_w01p + o4 * 4);
            float4 w1 = *(const float4*)(s_w01p + 16 + o4 * 4);
            float4 w2 = *(const float4*)(s_w01p + 32 + o4 * 4);
            h0[o4 * 4 + 0] = fmaxf(a.x + pA0 * w0.x + pA1 * w1.x + pA2 * w2.x, 0.f);
            h0[o4 * 4 + 1] = fmaxf(a.y + pA0 * w0.y + pA1 * w1.y + pA2 * w2.y, 0.f);
            h0[o4 * 4 + 2] = fmaxf(a.z + pA0 * w0.z + pA1 * w1.z + pA2 * w2.z, 0.f);
            h0[o4 * 4 + 3] = fmaxf(a.w + pA0 * w0.w + pA1 * w1.w + pA2 * w2.w, 0.f);
            h1[o4 * 4 + 0] = fmaxf(b.x + pB0 * w0.x + pB1 * w1.x + pB2 * w2.x, 0.f);
            h1[o4 * 4 + 1] = fmaxf(b.y + pB0 * w0.y + pB1 * w1.y + pB2 * w2.y, 0.f);
            h1[o4 * 4 + 2] = fmaxf(b.z + pB0 * w0.z + pB1 * w1.z + pB2 * w2.z, 0.f);
            h1[o4 * 4 + 3] = fmaxf(b.w + pB0 * w0.w + pB1 * w1.w + pB2 * w2.w, 0.f);
        }
    }

    // ---- symmetrized bilinear, weights from __constant__ ----
    ull e0p[8], e1p[8];
    {
        const ull* bB = (const ull*)s_blB;
#pragma unroll
        for (int q = 0; q < 8; q++) { ull b = bB[q]; e0p[q] = b; e1p[q] = b; }
    }
#pragma unroll
    for (int i = 0; i < 16; i++) {
#pragma unroll
        for (int jj = i; jj < 16; jj++) {
            const ull ga2 = bc2(h0[i] * h0[jj]);
            const ull gb2 = bc2(h1[i] * h1[jj]);
            const ulonglong2* wr = (const ulonglong2*)(c_w + (i * 16 + jj) * 16);
            ulonglong2 w0 = wr[0], w1 = wr[1], w2 = wr[2], w3 = wr[3];
            e0p[0] = fma2_(ga2, w0.x, e0p[0]); e1p[0] = fma2_(gb2, w0.x, e1p[0]);
            e0p[1] = fma2_(ga2, w0.y, e0p[1]); e1p[1] = fma2_(gb2, w0.y, e1p[1]);
            e0p[2] = fma2_(ga2, w1.x, e0p[2]); e1p[2] = fma2_(gb2, w1.x, e1p[2]);
            e0p[3] = fma2_(ga2, w1.y, e0p[3]); e1p[3] = fma2_(gb2, w1.y, e1p[3]);
            e0p[4] = fma2_(ga2, w2.x, e0p[4]); e1p[4] = fma2_(gb2, w2.x, e1p[4]);
            e0p[5] = fma2_(ga2, w2.y, e0p[5]); e1p[5] = fma2_(gb2, w2.y, e1p[5]);
            e0p[6] = fma2_(ga2, w3.x, e0p[6]); e1p[6] = fma2_(gb2, w3.x, e1p[6]);
            e0p[7] = fma2_(ga2, w3.y, e0p[7]); e1p[7] = fma2_(gb2, w3.y, e1p[7]);
        }
    }

    // ---- q vec ----
    float qa[3], qb[3];
#pragma unroll
    for (int d = 0; d < 3; d++) {
        qa[d] = fmaxf(fmaf(pA0, s_lp1f[d], fmaf(pA1, s_lp1f[4 + d], fmaf(pA2, s_lp1f[8 + d], s_lp1c[d]))), 0.f);
        qb[d] = fmaxf(fmaf(pB0, s_lp1f[d], fmaf(pB1, s_lp1f[4 + d], fmaf(pB2, s_lp1f[8 + d], s_lp1c[d]))), 0.f);
    }

    // ---- fused c2a(+q, BN folded)+relu+c2b(BN-scale folded) ----
    ull hb0p[4], hb1p[4];
    {
        const ull* shb = (const ull*)s_bn2bt;
#pragma unroll
        for (int m = 0; m < 4; m++) { ull b = shb[m]; hb0p[m] = b; hb1p[m] = b; }
    }
#pragma unroll
    for (int cb = 0; cb < 4; cb++) {
        ull a0p[8], a1p[8];
        {
            const ulonglong2* ccp = (const ulonglong2*)(s_c2aC + cb * 16);
            ulonglong2 c0 = ccp[0], c1 = ccp[1], c2 = ccp[2], c3 = ccp[3];
            a0p[0] = c0.x; a0p[1] = c0.y; a0p[2] = c1.x; a0p[3] = c1.y;
            a0p[4] = c2.x; a0p[5] = c2.y; a0p[6] = c3.x; a0p[7] = c3.y;
#pragma unroll
            for (int q = 0; q < 8; q++) a1p[q] = a0p[q];
        }
#pragma unroll
        for (int q8 = 0; q8 < 8; q8++) {
            float e0lo, e0hi, e1lo, e1hi;
            upk2(e0p[q8], e0lo, e0hi);
            upk2(e1p[q8], e1lo, e1hi);
#pragma unroll
            for (int hh = 0; hh < 2; hh++) {
                const ull va2 = bc2(hh ? e0hi : e0lo);
                const ull vb2 = bc2(hh ? e1hi : e1lo);
                const ulonglong2* wr = (const ulonglong2*)(c_w + 4096 + (2 * q8 + hh) * 64 + cb * 16);
                ulonglong2 w0 = wr[0], w1 = wr[1], w2 = wr[2], w3 = wr[3];
                a0p[0] = fma2_(va2, w0.x, a0p[0]); a1p[0] = fma2_(vb2, w0.x, a1p[0]);
                a0p[1] = fma2_(va2, w0.y, a0p[1]); a1p[1] = fma2_(vb2, w0.y, a1p[1]);
                a0p[2] = fma2_(va2, w1.x, a0p[2]); a1p[2] = fma2_(vb2, w1.x, a1p[2]);
                a0p[3] = fma2_(va2, w1.y, a0p[3]); a1p[3] = fma2_(vb2, w1.y, a1p[3]);
                a0p[4] = fma2_(va2, w2.x, a0p[4]); a1p[4] = fma2_(vb2, w2.x, a1p[4]);
                a0p[5] = fma2_(va2, w2.y, a0p[5]); a1p[5] = fma2_(vb2, w2.y, a1p[5]);
                a0p[6] = fma2_(va2, w3.x, a0p[6]); a1p[6] = fma2_(vb2, w3.x, a1p[6]);
                a0p[7] = fma2_(va2, w3.y, a0p[7]); a1p[7] = fma2_(vb2, w3.y, a1p[7]);
            }
        }
#pragma unroll
        for (int r = 0; r < 3; r++) {
            const ull va2 = bc2(qa[r]);
            const ull vb2 = bc2(qb[r]);
            const ulonglong2* wr = (const ulonglong2*)(s_c2aQ + r * 64 + cb * 16);
            ulonglong2 w0 = wr[0], w1 = wr[1], w2 = wr[2], w3 = wr[3];
            a0p[0] = fma2_(va2, w0.x, a0p[0]); a1p[0] = fma2_(vb2, w0.x, a1p[0]);
            a0p[1] = fma2_(va2, w0.y, a0p[1]); a1p[1] = fma2_(vb2, w0.y, a1p[1]);
            a0p[2] = fma2_(va2, w1.x, a0p[2]); a1p[2] = fma2_(vb2, w1.x, a1p[2]);
            a0p[3] = fma2_(va2, w1.y, a0p[3]); a1p[3] = fma2_(vb2, w1.y, a1p[3]);
            a0p[4] = fma2_(va2, w2.x, a0p[4]); a1p[4] = fma2_(vb2, w2.x, a1p[4]);
            a0p[5] = fma2_(va2, w2.y, a0p[5]); a1p[5] = fma2_(vb2, w2.y, a1p[5]);
            a0p[6] = fma2_(va2, w3.x, a0p[6]); a1p[6] = fma2_(vb2, w3.x, a1p[6]);
            a0p[7] = fma2_(va2, w3.y, a0p[7]); a1p[7] = fma2_(vb2, w3.y, a1p[7]);
        }
        // relu (BN folded) + c2b (scale folded)
#pragma unroll
        for (int q = 0; q < 8; q++) {
            float v00, v01, v10, v11;
            upk2(a0p[q], v00, v01); upk2(a1p[q], v10, v11);
            v00 = fmaxf(v00, 0.f);
            v01 = fmaxf(v01, 0.f);
            v10 = fmaxf(v10, 0.f);
            v11 = fmaxf(v11, 0.f);
            const ulonglong2* wb0 = (const ulonglong2*)(s_c2b + (cb * 16 + 2 * q) * 8);
            const ulonglong2* wb1 = (const ulonglong2*)(s_c2b + (cb * 16 + 2 * q + 1) * 8);
            ulonglong2 u0 = wb0[0], u1 = wb0[1];
            ulonglong2 u2 = wb1[0], u3 = wb1[1];
            const ull va2 = bc2(v00), vA2 = bc2(v01);
            const ull vb2 = bc2(v10), vB2 = bc2(v11);
            hb0p[0] = fma2_(va2, u0.x, hb0p[0]); hb0p[1] = fma2_(va2, u0.y, hb0p[1]);
            hb0p[2] = fma2_(va2, u1.x, hb0p[2]); hb0p[3] = fma2_(va2, u1.y, hb0p[3]);
            hb0p[0] = fma2_(vA2, u2.x, hb0p[0]); hb0p[1] = fma2_(vA2, u2.y, hb0p[1]);
            hb0p[2] = fma2_(vA2, u3.x, hb0p[2]); hb0p[3] = fma2_(vA2, u3.y, hb0p[3]);
            hb1p[0] = fma2_(vb2, u0.x, hb1p[0]); hb1p[1] = fma2_(vb2, u0.y, hb1p[1]);
            hb1p[2] = fma2_(vb2, u1.x, hb1p[2]); hb1p[3] = fma2_(vb2, u1.y, hb1p[3]);
            hb1p[0] = fma2_(vB2, u2.x, hb1p[0]); hb1p[1] = fma2_(vB2, u2.y, hb1p[1]);
            hb1p[2] = fma2_(vB2, u3.x, hb1p[2]); hb1p[3] = fma2_(vB2, u3.y, hb1p[3]);
        }
    }
    float hbs0[8], hbs1[8];
#pragma unroll
    for (int m = 0; m < 4; m++) {
        upk2(hb0p[m], hbs0[2 * m], hbs0[2 * m + 1]);
        upk2(hb1p[m], hbs1[2 * m], hbs1[2 * m + 1]);
    }
#pragma unroll
    for (int u = 0; u < 8; u++) {
        hbs0[u] = fmaxf(hbs0[u], 0.f);
        hbs1[u] = fmaxf(hbs1[u], 0.f);
    }

    // ---- logits (packed) ----
    ull lg0p[4], lg1p[4];
    {
        const ull* cbp = (const ull*)s_c2cb;
#pragma unroll
        for (int m = 0; m < 4; m++) { ull b = cbp[m]; lg0p[m] = b; lg1p[m] = b; }
    }
#pragma unroll
    for (int u = 0; u < 8; u++) {
        const ull h02 = bc2(hbs0[u]);
        const ull h12 = bc2(hbs1[u]);
        const ulonglong2* wr = (const ulonglong2*)(s_c2c + u * 8);
        ulonglong2 w0 = wr[0], w1 = wr[1];
        lg0p[0] = fma2_(h02, w0.x, lg0p[0]); lg1p[0] = fma2_(h12, w0.x, lg1p[0]);
        lg0p[1] = fma2_(h02, w0.y, lg0p[1]); lg1p[1] = fma2_(h12, w0.y, lg1p[1]);
        lg0p[2] = fma2_(h02, w1.x, lg0p[2]); lg1p[2] = fma2_(h12, w1.x, lg1p[2]);
        lg0p[3] = fma2_(h02, w1.y, lg0p[3]); lg1p[3] = fma2_(h12, w1.y, lg1p[3]);
    }

    // ---- softmax over 16 k-lanes (no max pass; |logits| << 1) ----
    float ws0[8], ws1[8];
#pragma unroll
    for (int m = 0; m < 4; m++) {
        float l0, l1;
        upk2(lg0p[m], l0, l1);
        ws0[2 * m] = __expf(l0); ws0[2 * m + 1] = __expf(l1);
        upk2(lg1p[m], l0, l1);
        ws1[2 * m] = __expf(l0); ws1[2 * m + 1] = __expf(l1);
    }
#pragma unroll
    for (int c = 0; c < 8; c++) {
        float s0 = ws0[c], s1 = ws1[c];
#pragma unroll
        for (int d = 8; d > 0; d >>= 1) {
            s0 += __shfl_xor_sync(0xffffffffu, s0, d);
            s1 += __shfl_xor_sync(0xffffffffu, s1, d);
        }
        ws0[c] = __fdividef(ws0[c], s0);
        ws1[c] = __fdividef(ws1[c], s1);
    }

    // ---- write per-pair state to smem for coalesced phase 2 ----
    {
        const int pair0 = pt0 * 16 + k;
        const int pair1 = (pt0 + 1) * 16 + k;
        ull* wsp = (ull*)s_ws;
#pragma unroll
        for (int m = 0; m < 4; m++) {
            wsp[pair0 * 4 + m] = pk2(ws0[2 * m], ws0[2 * m + 1]);
            wsp[pair1 * 4 + m] = pk2(ws1[2 * m], ws1[2 * m + 1]);
        }
        s_q[pair0 * 4 + 0] = qa[0]; s_q[pair0 * 4 + 1] = qa[1];
        s_q[pair0 * 4 + 2] = qa[2]; s_q[pair0 * 4 + 3] = 0.f;
        s_q[pair1 * 4 + 0] = qb[0]; s_q[pair1 * 4 + 1] = qb[1];
        s_q[pair1 * 4 + 2] = qb[2]; s_q[pair1 * 4 + 3] = 0.f;
        s_j[pair0] = j0;
        s_j[pair1] = j1;
    }
    __syncthreads();

    // ---- phase 2: coalesced epilogue. warp w -> points 4w..4w+3;
    //      lane -> channels (2*lane, 2*lane+1). out accumulated over k. ----
    {
        const int lane = tid & 31;
        const int w = tid >> 5;
        const ull l0 = ((const ull*)s_lp2)[lane];
        const ull l1 = ((const ull*)(s_lp2 + 64))[lane];
        const ull l2 = ((const ull*)(s_lp2 + 128))[lane];
        const ull lb = ((const ull*)s_lp2b)[lane];
        const ull* wsp = (const ull*)s_ws;
        const int m = lane & 3;
#pragma unroll
        for (int pt = w * 4; pt < w * 4 + 4; pt++) {
            const int nn = blockIdx.x * 32 + pt;
            const bool v = nn < n;
            ull acc = 0ull;
#pragma unroll
            for (int kk = 0; kk < 16; kk++) {
                const int pair = pt * 16 + kk;
                const int j = s_j[pair];
                float4 qv = *(const float4*)(s_q + pair * 4);
                const ull wsv = wsp[pair * 4 + m];
                const ull y = ((const ull*)(g_y + (size_t)j * 64))[lane];
                ull pe = fma2_(bc2(qv.x), l0,
                         fma2_(bc2(qv.y), l1,
                         fma2_(bc2(qv.z), l2, lb)));
                ull xv = mul2_(add2_(y, pe), wsv);
                if (v && xk_out)
                    ((ull*)(xk_out + ((size_t)nn * 16 + kk) * 64))[lane] = xv;
                acc = add2_(acc, xv);
            }
            if (v) ((ull*)(out + (size_t)nn * 64))[lane] = acc;
        }
    }
}

// ---------------------------------------------------------------------------
extern "C" void kernel_launch(void* const* d_in, const int* in_sizes, int n_in,
                              void* d_out, int out_size)
{
    const float* p    = (const float*)d_in[0];
    const float* x    = (const float*)d_in[1];
    const int*   knn  = (const int*)d_in[2];
    const float* w01  = (const float*)d_in[3];
    const float* b01  = (const float*)d_in[4];
    const float* blW  = (const float*)d_in[5];
    const float* blB  = (const float*)d_in[6];
    const float* lp1w = (const float*)d_in[7];
    const float* lp1b = (const float*)d_in[8];
    const float* bnpg = (const float*)d_in[9];
    const float* bnpb = (const float*)d_in[10];
    const float* bnpm = (const float*)d_in[11];
    const float* bnpv = (const float*)d_in[12];
    const float* lp2w = (const float*)d_in[13];
    const float* lp2b = (const float*)d_in[14];
    const float* c2aw = (const float*)d_in[15];
    const float* bn2ag = (const float*)d_in[16];
    const float* bn2ab = (const float*)d_in[17];
    const float* bn2am = (const float*)d_in[18];
    const float* bn2av = (const float*)d_in[19];
    const float* c2bw  = (const float*)d_in[20];
    const float* bn2bg = (const float*)d_in[21];
    const float* bn2bb = (const float*)d_in[22];
    const float* bn2bm = (const float*)d_in[23];
    const float* bn2bv = (const float*)d_in[24];
    const float* c2cw  = (const float*)d_in[25];
    const float* c2cb  = (const float*)d_in[26];
    const float* w03   = (const float*)d_in[27];
    const float* b03   = (const float*)d_in[28];

    const int n = in_sizes[0] / 3;
    float* out = (float*)d_out;

    const long long total = (long long)n * 64 + (long long)n * 16 * 64 +
                            (long long)n * 16 + (long long)n * 16 * 3;
    float* xk_out = nullptr;
    float* knn_out = nullptr;
    float* pr_out = nullptr;
    if ((long long)out_size >= total) {
        xk_out  = out + (size_t)n * 64;
        knn_out = xk_out + (size_t)n * 16 * 64;
        pr_out  = knn_out + (size_t)n * 16;
    }

    const int nb_data = (n + 63) / 64;
    prep_kernel<<<nb_data + 17, 256>>>(x, w03, b03, w01, b01,
                                       blW, c2aw, lp2w, lp2b,
                                       bn2ag, bn2ab, bn2am, bn2av,
                                       c2bw, bn2bg, bn2bv, n, nb_data);
    // Stage computed weight tables into __constant__ (single D2D memcpy node).
    float* d_wcat = nullptr; cudaGetSymbolAddress((void**)&d_wcat, g_wcat);
    cudaMemcpyToSymbolAsync(c_w, d_wcat, 5120 * sizeof(float), 0,
                            cudaMemcpyDeviceToDevice, 0);
    pm_main_kernel<<<(n + 31) / 32, 256>>>(p, knn, w01, blB,
                               lp1w, lp1b, bnpg, bnpb, bnpm, bnpv, lp2w, lp2b,
                               bn2bg, bn2bb, bn2bm, bn2bv,
                               c2cw, c2cb,
                               out, xk_out, knn_out, pr_out, n);
}

// round 14
// speedup vs baseline: 3.0868x; 1.0456x over previous
#include <cuda_runtime.h>
#include <cstdint>

#define MAXN 100352

typedef unsigned long long ull;

__device__ float g_y[MAXN * 64];   // x @ w03 + b03
__device__ float g_hx[MAXN * 16];  // x @ w01[3:] + b01
__device__ float g_wcat[5120];     // [0:4096)=blS symmetrized, [4096:5120)=c2aF
__device__ float g_c2aQ[192];      // folded q->c2a, BN2a-scale folded
__device__ float g_c2aC[64];       // folded const->c2a, BN2a scale+shift folded
__device__ float g_c2bF[512];      // c2b, BN2b-scale folded

// Uniform weights on the constant port (off the smem crossbar).
__constant__ float c_w[5120];      // [0:4096)=blS, [4096:5120)=c2a

// ---- packed f32x2 helpers (FFMA2) ----
__device__ __forceinline__ ull pk2(float lo, float hi) {
    ull r; asm("mov.b64 %0,{%1,%2};" : "=l"(r) : "f"(lo), "f"(hi)); return r;
}
__device__ __forceinline__ ull bc2(float v) { return pk2(v, v); }
__device__ __forceinline__ void upk2(ull v, float& lo, float& hi) {
    asm("mov.b64 {%0,%1},%2;" : "=f"(lo), "=f"(hi) : "l"(v));
}
__device__ __forceinline__ ull fma2_(ull a, ull b, ull c) {
    ull d; asm("fma.rn.f32x2 %0,%1,%2,%3;" : "=l"(d) : "l"(a), "l"(b), "l"(c)); return d;
}
__device__ __forceinline__ ull add2_(ull a, ull b) {
    ull d; asm("add.rn.f32x2 %0,%1,%2;" : "=l"(d) : "l"(a), "l"(b)); return d;
}
__device__ __forceinline__ ull mul2_(ull a, ull b) {
    ull d; asm("mul.rn.f32x2 %0,%1,%2;" : "=l"(d) : "l"(a), "l"(b)); return d;
}

// ---------------------------------------------------------------------------
// Prep kernel: data blocks compute y & hx; 17 tail blocks do weight setup.
// ---------------------------------------------------------------------------
__global__ void __launch_bounds__(256) prep_kernel(
    const float* __restrict__ x, const float* __restrict__ w03,
    const float* __restrict__ b03, const float* __restrict__ w01,
    const float* __restrict__ b01,
    const float* __restrict__ blW, const float* __restrict__ c2aw,
    const float* __restrict__ lp2w, const float* __restrict__ lp2b,
    const float* __restrict__ bn2ag, const float* __restrict__ bn2ab,
    const float* __restrict__ bn2am, const float* __restrict__ bn2av,
    const float* __restrict__ c2bw, const float* __restrict__ bn2bg,
    const float* __restrict__ bn2bv,
    int n, int nb_data)
{
    const int tid = threadIdx.x;
    if (blockIdx.x >= nb_data) {
        const int sb = blockIdx.x - nb_data;
        if (sb < 16) {
            const int id = sb * 256 + tid;
            const int o = id & 15;
            const int pr = id >> 4;
            const int jj = pr & 15;
            const int i = pr >> 4;
            float v;
            if (i < jj)       v = blW[o * 256 + i * 16 + jj] + blW[o * 256 + jj * 16 + i];
            else if (i == jj) v = blW[o * 256 + i * 16 + i];
            else              v = 0.f;
            g_wcat[id] = v;
        } else {
            __shared__ float sM[48], s0[16];
            __shared__ float sca[64], sha[64];
            if (tid < 48) {
                const int r = tid >> 4, u = tid & 15;
                sM[tid] = lp2w[r * 64 + u] + lp2w[r * 64 + 16 + u] +
                          lp2w[r * 64 + 32 + u] + lp2w[r * 64 + 48 + u];
            }
            if (tid >= 48 && tid < 64) {
                const int u = tid - 48;
                s0[u] = lp2b[u] + lp2b[16 + u] + lp2b[32 + u] + lp2b[48 + u];
            }
            if (tid >= 64 && tid < 128) {
                const int c = tid - 64;
                float sc = bn2ag[c] * rsqrtf(bn2av[c] + 1e-5f);
                sca[c] = sc;
                sha[c] = bn2ab[c] - bn2am[c] * sc;
            }
            __syncthreads();
            if (tid < 192) {
                const int r = tid >> 6, c = tid & 63;
                float acc = 0.f;
#pragma unroll
                for (int u = 0; u < 16; u++)
                    acc += sM[r * 16 + u] * c2aw[(16 + u) * 64 + c];
                g_c2aQ[r * 64 + c] = acc * sca[c];
            } else {
                const int c = tid - 192;
                float acc = 0.f;
#pragma unroll
                for (int u = 0; u < 16; u++)
                    acc += s0[u] * c2aw[(16 + u) * 64 + c];
                g_c2aC[c] = acc * sca[c] + sha[c];
            }
#pragma unroll
            for (int t = 0; t < 4; t++) {
                const int i = tid + t * 256;
                g_wcat[4096 + i] = c2aw[i] * sca[i & 63];
            }
#pragma unroll
            for (int t = 0; t < 2; t++) {
                const int i = tid + t * 256;
                const int u = i & 7;
                g_c2bF[i] = c2bw[i] * (bn2bg[u] * rsqrtf(bn2bv[u] + 1e-5f));
            }
        }
        return;
    }

    __shared__ float sw[4096];
    __shared__ float sw1[1024];
    __shared__ float sx[32][64];
    for (int i = tid; i < 1024; i += 256)
        ((float4*)sw)[i] = ((const float4*)w03)[i];
    for (int i = tid; i < 256; i += 256)
        ((float4*)sw1)[i] = ((const float4*)(w01 + 48))[i];
    const int base = blockIdx.x * 32;
    {
        const int c4 = tid & 15;
        const int r = tid >> 4;
#pragma unroll
        for (int a = 0; a < 2; a++) {
            const int row = base + r + a * 16;
            float4 v = make_float4(0.f, 0.f, 0.f, 0.f);
            if (row < n) v = ((const float4*)(x + (size_t)row * 64))[c4];
            ((float4*)sx[r + a * 16])[c4] = v;
        }
    }
    __syncthreads();

    {
        const int rq = tid >> 5;
        const int cp = tid & 31;
        const ull bcp = ((const ull*)b03)[cp];
        ull acc0 = bcp, acc1 = bcp, acc2 = bcp, acc3 = bcp;
#pragma unroll 8
        for (int d = 0; d < 64; d++) {
            const ull w2 = ((const ull*)(sw + d * 64))[cp];
            acc0 = fma2_(bc2(sx[rq * 4 + 0][d]), w2, acc0);
            acc1 = fma2_(bc2(sx[rq * 4 + 1][d]), w2, acc1);
            acc2 = fma2_(bc2(sx[rq * 4 + 2][d]), w2, acc2);
            acc3 = fma2_(bc2(sx[rq * 4 + 3][d]), w2, acc3);
        }
        const int r0 = base + rq * 4;
        if (r0 + 0 < n) ((ull*)(g_y + (size_t)(r0 + 0) * 64))[cp] = acc0;
        if (r0 + 1 < n) ((ull*)(g_y + (size_t)(r0 + 1) * 64))[cp] = acc1;
        if (r0 + 2 < n) ((ull*)(g_y + (size_t)(r0 + 2) * 64))[cp] = acc2;
        if (r0 + 3 < n) ((ull*)(g_y + (size_t)(r0 + 3) * 64))[cp] = acc3;
    }
    {
        const int r = tid >> 3;
        const int o8 = tid & 7;
        ull acc = ((const ull*)b01)[o8];
#pragma unroll 8
        for (int d = 0; d < 64; d++)
            acc = fma2_(bc2(sx[r][d]), ((const ull*)(sw1 + d * 16))[o8], acc);
        const int row = base + r;
        if (row < n) ((ull*)(g_hx + (size_t)row * 16))[o8] = acc;
    }
}

// ---------------------------------------------------------------------------
// Main kernel: 256 threads, 32 points/block, two-phase (R10 structure).
// Phase 1 per-warp covers points 4w..4w+3; phase 2 reads ONLY that warp's
// data, so the inter-phase barrier is __syncwarp (no block barrier).
// ---------------------------------------------------------------------------
__global__ void __launch_bounds__(256, 2) pm_main_kernel(
    const float* __restrict__ p,
    const int* __restrict__ knn,
    const float* __restrict__ w01, const float* __restrict__ blB,
    const float* __restrict__ lp1w, const float* __restrict__ lp1b,
    const float* __restrict__ bnpg, const float* __restrict__ bnpb,
    const float* __restrict__ bnpm, const float* __restrict__ bnpv,
    const float* __restrict__ lp2w, const float* __restrict__ lp2b,
    const float* __restrict__ bn2bg, const float* __restrict__ bn2bb,
    const float* __restrict__ bn2bm, const float* __restrict__ bn2bv,
    const float* __restrict__ c2cw, const float* __restrict__ c2cb,
    float* __restrict__ out, float* __restrict__ xk_out,
    float* __restrict__ knn_out, float* __restrict__ pr_out,
    int n)
{
    __shared__ __align__(16) float s_ws[512 * 8];   // softmax weights per pair
    __shared__ __align__(16) float s_q[512 * 4];    // q vec per pair
    __shared__ int   s_j[512];                      // gather index per pair
    __shared__ __align__(16) float s_c2aQ[192];
    __shared__ __align__(16) float s_c2aC[64];
    __shared__ __align__(16) float s_c2b[512];
    __shared__ __align__(16) float s_c2c[64];
    __shared__ __align__(16) float s_lp2[192], s_lp2b[64];
    __shared__ __align__(16) float s_w01p[48];
    __shared__ __align__(16) float s_blB[16];
    __shared__ __align__(16) float s_lp1f[12], s_lp1c[4];
    __shared__ __align__(16) float s_bn2bt[8], s_c2cb[8];

    const int tid = threadIdx.x;

    // ---- staging (small tables only) ----
    if (tid < 128) ((float4*)s_c2b)[tid] = ((const float4*)g_c2bF)[tid];
    if (tid < 192) { s_c2aQ[tid] = g_c2aQ[tid]; s_lp2[tid] = lp2w[tid]; }
    if (tid < 64) {
        s_c2aC[tid] = g_c2aC[tid];
        s_lp2b[tid] = lp2b[tid];
        s_c2c[tid] = c2cw[tid];
    }
    if (tid < 48) s_w01p[tid] = w01[tid];
    if (tid < 16) s_blB[tid] = blB[tid];
    if (tid < 8) {
        float sc = bn2bg[tid] * rsqrtf(bn2bv[tid] + 1e-5f);
        s_bn2bt[tid] = bn2bb[tid] - bn2bm[tid] * sc;
        s_c2cb[tid] = c2cb[tid];
    }
    if (tid < 3) {
        const int d = tid;
        float sc = bnpg[d] * rsqrtf(bnpv[d] + 1e-5f);
        s_lp1f[0 + d] = lp1w[0 * 3 + d] * sc;
        s_lp1f[4 + d] = lp1w[1 * 3 + d] * sc;
        s_lp1f[8 + d] = lp1w[2 * 3 + d] * sc;
        s_lp1c[d] = (lp1b[d] - bnpm[d]) * sc + bnpb[d];
    }
    __syncthreads();

    // ---- pair setup ----
    const int k = tid & 15;
    const int half = (tid >> 4) & 1;
    const int wrp = tid >> 5;
    const int pt0 = wrp * 4 + half * 2;             // point within block
    const int base = blockIdx.x * 32 + pt0;
    const int nn0 = base, nn1 = base + 1;
    const bool v0 = nn0 < n, v1 = nn1 < n;
    const int nc0 = v0 ? nn0 : (n > 0 ? n - 1 : 0);
    const int nc1 = v1 ? nn1 : (n > 0 ? n - 1 : 0);
    const int j0 = knn[(size_t)nc0 * 16 + k];
    const int j1 = knn[(size_t)nc1 * 16 + k];

    const float pA0 = p[(size_t)j0 * 3 + 0] - p[(size_t)nc0 * 3 + 0];
    const float pA1 = p[(size_t)j0 * 3 + 1] - p[(size_t)nc0 * 3 + 1];
    const float pA2 = p[(size_t)j0 * 3 + 2] - p[(size_t)nc0 * 3 + 2];
    const float pB0 = p[(size_t)j1 * 3 + 0] - p[(size_t)nc1 * 3 + 0];
    const float pB1 = p[(size_t)j1 * 3 + 1] - p[(size_t)nc1 * 3 + 1];
    const float pB2 = p[(size_t)j1 * 3 + 2] - p[(size_t)nc1 * 3 + 2];
    if (v0 && pr_out) {
        pr_out[((size_t)nn0 * 16 + k) * 3 + 0] = pA0;
        pr_out[((size_t)nn0 * 16 + k) * 3 + 1] = pA1;
        pr_out[((size_t)nn0 * 16 + k) * 3 + 2] = pA2;
    }
    if (v1 && pr_out) {
        pr_out[((size_t)nn1 * 16 + k) * 3 + 0] = pB0;
        pr_out[((size_t)nn1 * 16 + k) * 3 + 1] = pB1;
        pr_out[((size_t)nn1 * 16 + k) * 3 + 2] = pB2;
    }
    if (v0 && knn_out) knn_out[(size_t)nn0 * 16 + k] = (float)j0;
    if (v1 && knn_out) knn_out[(size_t)nn1 * 16 + k] = (float)j1;

    // ---- h = relu(hx[j] + pr @ w01p) ----
    float h0[16], h1[16];
    {
        const float4* hxa = (const float4*)(g_hx + (size_t)j0 * 16);
        const float4* hxb = (const float4*)(g_hx + (size_t)j1 * 16);
#pragma unroll
        for (int o4 = 0; o4 < 4; o4++) {
            float4 a = hxa[o4], b = hxb[o4];
            float4 w0 = *(const float4*)(s_w01p + o4 * 4);
            float4 w1 = *(const float4*)(s_w01p + 16 + o4 * 4);
            float4 w2 = *(const float4*)(s_w01p + 32 + o4 * 4);
            h0[o4 * 4 + 0] = fmaxf(a.x + pA0 * w0.x + pA1 * w1.x + pA2 * w2.x, 0.f);
            h0[o4 * 4 + 1] = fmaxf(a.y + pA0 * w0.y + pA1 * w1.y + pA2 * w2.y, 0.f);
            h0[o4 * 4 + 2] = fmaxf(a.z + pA0 * w0.z + pA1 * w1.z + pA2 * w2.z, 0.f);
            h0[o4 * 4 + 3] = fmaxf(a.w + pA0 * w0.w + pA1 * w1.w + pA2 * w2.w, 0.f);
            h1[o4 * 4 + 0] = fmaxf(b.x + pB0 * w0.x + pB1 * w1.x + pB2 * w2.x, 0.f);
            h1[o4 * 4 + 1] = fmaxf(b.y + pB0 * w0.y + pB1 * w1.y + pB2 * w2.y, 0.f);
            h1[o4 * 4 + 2] = fmaxf(b.z + pB0 * w0.z + pB1 * w1.z + pB2 * w2.z, 0.f);
            h1[o4 * 4 + 3] = fmaxf(b.w + pB0 * w0.w + pB1 * w1.w + pB2 * w2.w, 0.f);
        }
    }

    // ---- symmetrized bilinear, weights from __constant__ ----
    ull e0p[8], e1p[8];
    {
        const ull* bB = (const ull*)s_blB;
#pragma unroll
        for (int q = 0; q < 8; q++) { ull b = bB[q]; e0p[q] = b; e1p[q] = b; }
    }
#pragma unroll
    for (int i = 0; i < 16; i++) {
#pragma unroll
        for (int jj = i; jj < 16; jj++) {
            const ull ga2 = bc2(h0[i] * h0[jj]);
            const ull gb2 = bc2(h1[i] * h1[jj]);
            const ulonglong2* wr = (const ulonglong2*)(c_w + (i * 16 + jj) * 16);
            ulonglong2 w0 = wr[0], w1 = wr[1], w2 = wr[2], w3 = wr[3];
            e0p[0] = fma2_(ga2, w0.x, e0p[0]); e1p[0] = fma2_(gb2, w0.x, e1p[0]);
            e0p[1] = fma2_(ga2, w0.y, e0p[1]); e1p[1] = fma2_(gb2, w0.y, e1p[1]);
            e0p[2] = fma2_(ga2, w1.x, e0p[2]); e1p[2] = fma2_(gb2, w1.x, e1p[2]);
            e0p[3] = fma2_(ga2, w1.y, e0p[3]); e1p[3] = fma2_(gb2, w1.y, e1p[3]);
            e0p[4] = fma2_(ga2, w2.x, e0p[4]); e1p[4] = fma2_(gb2, w2.x, e1p[4]);
            e0p[5] = fma2_(ga2, w2.y, e0p[5]); e1p[5] = fma2_(gb2, w2.y, e1p[5]);
            e0p[6] = fma2_(ga2, w3.x, e0p[6]); e1p[6] = fma2_(gb2, w3.x, e1p[6]);
            e0p[7] = fma2_(ga2, w3.y, e0p[7]); e1p[7] = fma2_(gb2, w3.y, e1p[7]);
        }
    }

    // ---- q vec ----
    float qa[3], qb[3];
#pragma unroll
    for (int d = 0; d < 3; d++) {
        qa[d] = fmaxf(fmaf(pA0, s_lp1f[d], fmaf(pA1, s_lp1f[4 + d], fmaf(pA2, s_lp1f[8 + d], s_lp1c[d]))), 0.f);
        qb[d] = fmaxf(fmaf(pB0, s_lp1f[d], fmaf(pB1, s_lp1f[4 + d], fmaf(pB2, s_lp1f[8 + d], s_lp1c[d]))), 0.f);
    }

    // ---- fused c2a(+q, BN folded)+relu+c2b(BN-scale folded) ----
    ull hb0p[4], hb1p[4];
    {
        const ull* shb = (const ull*)s_bn2bt;
#pragma unroll
        for (int m = 0; m < 4; m++) { ull b = shb[m]; hb0p[m] = b; hb1p[m] = b; }
    }
#pragma unroll
    for (int cb = 0; cb < 4; cb++) {
        ull a0p[8], a1p[8];
        {
            const ulonglong2* ccp = (const ulonglong2*)(s_c2aC + cb * 16);
            ulonglong2 c0 = ccp[0], c1 = ccp[1], c2 = ccp[2], c3 = ccp[3];
            a0p[0] = c0.x; a0p[1] = c0.y; a0p[2] = c1.x; a0p[3] = c1.y;
            a0p[4] = c2.x; a0p[5] = c2.y; a0p[6] = c3.x; a0p[7] = c3.y;
#pragma unroll
            for (int q = 0; q < 8; q++) a1p[q] = a0p[q];
        }
#pragma unroll
        for (int q8 = 0; q8 < 8; q8++) {
            float e0lo, e0hi, e1lo, e1hi;
            upk2(e0p[q8], e0lo, e0hi);
            upk2(e1p[q8], e1lo, e1hi);
#pragma unroll
            for (int hh = 0; hh < 2; hh++) {
                const ull va2 = bc2(hh ? e0hi : e0lo);
                const ull vb2 = bc2(hh ? e1hi : e1lo);
                const ulonglong2* wr = (const ulonglong2*)(c_w + 4096 + (2 * q8 + hh) * 64 + cb * 16);
                ulonglong2 w0 = wr[0], w1 = wr[1], w2 = wr[2], w3 = wr[3];
                a0p[0] = fma2_(va2, w0.x, a0p[0]); a1p[0] = fma2_(vb2, w0.x, a1p[0]);
                a0p[1] = fma2_(va2, w0.y, a0p[1]); a1p[1] = fma2_(vb2, w0.y, a1p[1]);
                a0p[2] = fma2_(va2, w1.x, a0p[2]); a1p[2] = fma2_(vb2, w1.x, a1p[2]);
                a0p[3] = fma2_(va2, w1.y, a0p[3]); a1p[3] = fma2_(vb2, w1.y, a1p[3]);
                a0p[4] = fma2_(va2, w2.x, a0p[4]); a1p[4] = fma2_(vb2, w2.x, a1p[4]);
                a0p[5] = fma2_(va2, w2.y, a0p[5]); a1p[5] = fma2_(vb2, w2.y, a1p[5]);
                a0p[6] = fma2_(va2, w3.x, a0p[6]); a1p[6] = fma2_(vb2, w3.x, a1p[6]);
                a0p[7] = fma2_(va2, w3.y, a0p[7]); a1p[7] = fma2_(vb2, w3.y, a1p[7]);
            }
        }
#pragma unroll
        for (int r = 0; r < 3; r++) {
            const ull va2 = bc2(qa[r]);
            const ull vb2 = bc2(qb[r]);
            const ulonglong2* wr = (const ulonglong2*)(s_c2aQ + r * 64 + cb * 16);
            ulonglong2 w0 = wr[0], w1 = wr[1], w2 = wr[2], w3 = wr[3];
            a0p[0] = fma2_(va2, w0.x, a0p[0]); a1p[0] = fma2_(vb2, w0.x, a1p[0]);
            a0p[1] = fma2_(va2, w0.y, a0p[1]); a1p[1] = fma2_(vb2, w0.y, a1p[1]);
            a0p[2] = fma2_(va2, w1.x, a0p[2]); a1p[2] = fma2_(vb2, w1.x, a1p[2]);
            a0p[3] = fma2_(va2, w1.y, a0p[3]); a1p[3] = fma2_(vb2, w1.y, a1p[3]);
            a0p[4] = fma2_(va2, w2.x, a0p[4]); a1p[4] = fma2_(vb2, w2.x, a1p[4]);
            a0p[5] = fma2_(va2, w2.y, a0p[5]); a1p[5] = fma2_(vb2, w2.y, a1p[5]);
            a0p[6] = fma2_(va2, w3.x, a0p[6]); a1p[6] = fma2_(vb2, w3.x, a1p[6]);
            a0p[7] = fma2_(va2, w3.y, a0p[7]); a1p[7] = fma2_(vb2, w3.y, a1p[7]);
        }
        // relu (BN folded) + c2b (scale folded)
#pragma unroll
        for (int q = 0; q < 8; q++) {
            float v00, v01, v10, v11;
            upk2(a0p[q], v00, v01); upk2(a1p[q], v10, v11);
            v00 = fmaxf(v00, 0.f);
            v01 = fmaxf(v01, 0.f);
            v10 = fmaxf(v10, 0.f);
            v11 = fmaxf(v11, 0.f);
            const ulonglong2* wb0 = (const ulonglong2*)(s_c2b + (cb * 16 + 2 * q) * 8);
            const ulonglong2* wb1 = (const ulonglong2*)(s_c2b + (cb * 16 + 2 * q + 1) * 8);
            ulonglong2 u0 = wb0[0], u1 = wb0[1];
            ulonglong2 u2 = wb1[0], u3 = wb1[1];
            const ull va2 = bc2(v00), vA2 = bc2(v01);
            const ull vb2 = bc2(v10), vB2 = bc2(v11);
            hb0p[0] = fma2_(va2, u0.x, hb0p[0]); hb0p[1] = fma2_(va2, u0.y, hb0p[1]);
            hb0p[2] = fma2_(va2, u1.x, hb0p[2]); hb0p[3] = fma2_(va2, u1.y, hb0p[3]);
            hb0p[0] = fma2_(vA2, u2.x, hb0p[0]); hb0p[1] = fma2_(vA2, u2.y, hb0p[1]);
            hb0p[2] = fma2_(vA2, u3.x, hb0p[2]); hb0p[3] = fma2_(vA2, u3.y, hb0p[3]);
            hb1p[0] = fma2_(vb2, u0.x, hb1p[0]); hb1p[1] = fma2_(vb2, u0.y, hb1p[1]);
            hb1p[2] = fma2_(vb2, u1.x, hb1p[2]); hb1p[3] = fma2_(vb2, u1.y, hb1p[3]);
            hb1p[0] = fma2_(vB2, u2.x, hb1p[0]); hb1p[1] = fma2_(vB2, u2.y, hb1p[1]);
            hb1p[2] = fma2_(vB2, u3.x, hb1p[2]); hb1p[3] = fma2_(vB2, u3.y, hb1p[3]);
        }
    }
    float hbs0[8], hbs1[8];
#pragma unroll
    for (int m = 0; m < 4; m++) {
        upk2(hb0p[m], hbs0[2 * m], hbs0[2 * m + 1]);
        upk2(hb1p[m], hbs1[2 * m], hbs1[2 * m + 1]);
    }
#pragma unroll
    for (int u = 0; u < 8; u++) {
        hbs0[u] = fmaxf(hbs0[u], 0.f);
        hbs1[u] = fmaxf(hbs1[u], 0.f);
    }

    // ---- logits (packed) ----
    ull lg0p[4], lg1p[4];
    {
        const ull* cbp = (const ull*)s_c2cb;
#pragma unroll
        for (int m = 0; m < 4; m++) { ull b = cbp[m]; lg0p[m] = b; lg1p[m] = b; }
    }
#pragma unroll
    for (int u = 0; u < 8; u++) {
        const ull h02 = bc2(hbs0[u]);
        const ull h12 = bc2(hbs1[u]);
        const ulonglong2* wr = (const ulonglong2*)(s_c2c + u * 8);
        ulonglong2 w0 = wr[0], w1 = wr[1];
        lg0p[0] = fma2_(h02, w0.x, lg0p[0]); lg1p[0] = fma2_(h12, w0.x, lg1p[0]);
        lg0p[1] = fma2_(h02, w0.y, lg0p[1]); lg1p[1] = fma2_(h12, w0.y, lg1p[1]);
        lg0p[2] = fma2_(h02, w1.x, lg0p[2]); lg1p[2] = fma2_(h12, w1.x, lg1p[2]);
        lg0p[3] = fma2_(h02, w1.y, lg0p[3]); lg1p[3] = fma2_(h12, w1.y, lg1p[3]);
    }

    // ---- softmax over 16 k-lanes (no max pass; |logits| << 1) ----
    float ws0[8], ws1[8];
#pragma unroll
    for (int m = 0; m < 4; m++) {
        float l0, l1;
        upk2(lg0p[m], l0, l1);
        ws0[2 * m] = __expf(l0); ws0[2 * m + 1] = __expf(l1);
        upk2(lg1p[m], l0, l1);
        ws1[2 * m] = __expf(l0); ws1[2 * m + 1] = __expf(l1);
    }
#pragma unroll
    for (int c = 0; c < 8; c++) {
        float s0 = ws0[c], s1 = ws1[c];
#pragma unroll
        for (int d = 8; d > 0; d >>= 1) {
            s0 += __shfl_xor_sync(0xffffffffu, s0, d);
            s1 += __shfl_xor_sync(0xffffffffu, s1, d);
        }
        ws0[c] = __fdividef(ws0[c], s0);
        ws1[c] = __fdividef(ws1[c], s1);
    }

    // ---- write per-pair state to smem (consumed by THIS warp only) ----
    {
        const int pair0 = pt0 * 16 + k;
        const int pair1 = (pt0 + 1) * 16 + k;
        ull* wsp = (ull*)s_ws;
#pragma unroll
        for (int m = 0; m < 4; m++) {
            wsp[pair0 * 4 + m] = pk2(ws0[2 * m], ws0[2 * m + 1]);
            wsp[pair1 * 4 + m] = pk2(ws1[2 * m], ws1[2 * m + 1]);
        }
        s_q[pair0 * 4 + 0] = qa[0]; s_q[pair0 * 4 + 1] = qa[1];
        s_q[pair0 * 4 + 2] = qa[2]; s_q[pair0 * 4 + 3] = 0.f;
        s_q[pair1 * 4 + 0] = qb[0]; s_q[pair1 * 4 + 1] = qb[1];
        s_q[pair1 * 4 + 2] = qb[2]; s_q[pair1 * 4 + 3] = 0.f;
        s_j[pair0] = j0;
        s_j[pair1] = j1;
    }
    __syncwarp();   // producer warp == consumer warp; no block barrier needed

    // ---- phase 2: coalesced epilogue. warp w -> points 4w..4w+3;
    //      lane -> channels (2*lane, 2*lane+1). out accumulated over k. ----
    {
        const int lane = tid & 31;
        const int w = tid >> 5;
        const ull l0 = ((const ull*)s_lp2)[lane];
        const ull l1 = ((const ull*)(s_lp2 + 64))[lane];
        const ull l2 = ((const ull*)(s_lp2 + 128))[lane];
        const ull lb = ((const ull*)s_lp2b)[lane];
        const ull* wsp = (const ull*)s_ws;
        const int m = lane & 3;
#pragma unroll
        for (int pt = w * 4; pt < w * 4 + 4; pt++) {
            const int nn = blockIdx.x * 32 + pt;
            const bool v = nn < n;
            ull acc = 0ull;
#pragma unroll
            for (int kk = 0; kk < 16; kk++) {
                const int pair = pt * 16 + kk;
                const int j = s_j[pair];
                float4 qv = *(const float4*)(s_q + pair * 4);
                const ull wsv = wsp[pair * 4 + m];
                const ull y = ((const ull*)(g_y + (size_t)j * 64))[lane];
                ull pe = fma2_(bc2(qv.x), l0,
                         fma2_(bc2(qv.y), l1,
                         fma2_(bc2(qv.z), l2, lb)));
                ull xv = mul2_(add2_(y, pe), wsv);
                if (v && xk_out)
                    ((ull*)(xk_out + ((size_t)nn * 16 + kk) * 64))[lane] = xv;
                acc = add2_(acc, xv);
            }
            if (v) ((ull*)(out + (size_t)nn * 64))[lane] = acc;
        }
    }
}

// ---------------------------------------------------------------------------
extern "C" void kernel_launch(void* const* d_in, const int* in_sizes, int n_in,
                              void* d_out, int out_size)
{
    const float* p    = (const float*)d_in[0];
    const float* x    = (const float*)d_in[1];
    const int*   knn  = (const int*)d_in[2];
    const float* w01  = (const float*)d_in[3];
    const float* b01  = (const float*)d_in[4];
    const float* blW  = (const float*)d_in[5];
    const float* blB  = (const float*)d_in[6];
    const float* lp1w = (const float*)d_in[7];
    const float* lp1b = (const float*)d_in[8];
    const float* bnpg = (const float*)d_in[9];
    const float* bnpb = (const float*)d_in[10];
    const float* bnpm = (const float*)d_in[11];
    const float* bnpv = (const float*)d_in[12];
    const float* lp2w = (const float*)d_in[13];
    const float* lp2b = (const float*)d_in[14];
    const float* c2aw = (const float*)d_in[15];
    const float* bn2ag = (const float*)d_in[16];
    const float* bn2ab = (const float*)d_in[17];
    const float* bn2am = (const float*)d_in[18];
    const float* bn2av = (const float*)d_in[19];
    const float* c2bw  = (const float*)d_in[20];
    const float* bn2bg = (const float*)d_in[21];
    const float* bn2bb = (const float*)d_in[22];
    const float* bn2bm = (const float*)d_in[23];
    const float* bn2bv = (const float*)d_in[24];
    const float* c2cw  = (const float*)d_in[25];
    const float* c2cb  = (const float*)d_in[26];
    const float* w03   = (const float*)d_in[27];
    const float* b03   = (const float*)d_in[28];

    const int n = in_sizes[0] / 3;
    float* out = (float*)d_out;

    const long long total = (long long)n * 64 + (long long)n * 16 * 64 +
                            (long long)n * 16 + (long long)n * 16 * 3;
    float* xk_out = nullptr;
    float* knn_out = nullptr;
    float* pr_out = nullptr;
    if ((long long)out_size >= total) {
        xk_out  = out + (size_t)n * 64;
        knn_out = xk_out + (size_t)n * 16 * 64;
        pr_out  = knn_out + (size_t)n * 16;
    }

    const int nb_data = (n + 31) / 32;
    prep_kernel<<<nb_data + 17, 256>>>(x, w03, b03, w01, b01,
                                       blW, c2aw, lp2w, lp2b,
                                       bn2ag, bn2ab, bn2am, bn2av,
                                       c2bw, bn2bg, bn2bv, n, nb_data);
    // Stage computed weight tables into __constant__ (single D2D memcpy node).
    float* d_wcat = nullptr; cudaGetSymbolAddress((void**)&d_wcat, g_wcat);
    cudaMemcpyToSymbolAsync(c_w, d_wcat, 5120 * sizeof(float), 0,
                            cudaMemcpyDeviceToDevice, 0);
    pm_main_kernel<<<(n + 31) / 32, 256>>>(p, knn, w01, blB,
                               lp1w, lp1b, bnpg, bnpb, bnpm, bnpv, lp2w, lp2b,
                               bn2bg, bn2bb, bn2bm, bn2bv,
                               c2cw, c2cb,
                               out, xk_out, knn_out, pr_out, n);
}

// round 15
// speedup vs baseline: 3.4318x; 1.1118x over previous
#include <cuda_runtime.h>
#include <cstdint>

#define MAXN 100352

typedef unsigned long long ull;

__device__ float g_y[MAXN * 64];   // x @ w03 + b03
__device__ float g_hx[MAXN * 16];  // x @ w01[3:] + b01
__device__ float g_wcat[5120];     // [0:4096)=blS symmetrized, [4096:5120)=c2aF
__device__ float g_c2aQ[192];      // folded q->c2a, BN2a-scale folded
__device__ float g_c2aC[64];       // folded const->c2a, BN2a scale+shift folded
__device__ float g_c2bF[512];      // c2b, BN2b-scale folded

// Uniform weights on the constant port (off the smem crossbar).
__constant__ float c_w[5120];      // [0:4096)=blS, [4096:5120)=c2a

// ---- packed f32x2 helpers (FFMA2) ----
__device__ __forceinline__ ull pk2(float lo, float hi) {
    ull r; asm("mov.b64 %0,{%1,%2};" : "=l"(r) : "f"(lo), "f"(hi)); return r;
}
__device__ __forceinline__ ull bc2(float v) { return pk2(v, v); }
__device__ __forceinline__ void upk2(ull v, float& lo, float& hi) {
    asm("mov.b64 {%0,%1},%2;" : "=f"(lo), "=f"(hi) : "l"(v));
}
__device__ __forceinline__ ull fma2_(ull a, ull b, ull c) {
    ull d; asm("fma.rn.f32x2 %0,%1,%2,%3;" : "=l"(d) : "l"(a), "l"(b), "l"(c)); return d;
}
__device__ __forceinline__ ull add2_(ull a, ull b) {
    ull d; asm("add.rn.f32x2 %0,%1,%2;" : "=l"(d) : "l"(a), "l"(b)); return d;
}
__device__ __forceinline__ ull mul2_(ull a, ull b) {
    ull d; asm("mul.rn.f32x2 %0,%1,%2;" : "=l"(d) : "l"(a), "l"(b)); return d;
}

// ---------------------------------------------------------------------------
// Prep kernel: data blocks compute y & hx; 17 tail blocks do weight setup.
// ---------------------------------------------------------------------------
__global__ void __launch_bounds__(256) prep_kernel(
    const float* __restrict__ x, const float* __restrict__ w03,
    const float* __restrict__ b03, const float* __restrict__ w01,
    const float* __restrict__ b01,
    const float* __restrict__ blW, const float* __restrict__ c2aw,
    const float* __restrict__ lp2w, const float* __restrict__ lp2b,
    const float* __restrict__ bn2ag, const float* __restrict__ bn2ab,
    const float* __restrict__ bn2am, const float* __restrict__ bn2av,
    const float* __restrict__ c2bw, const float* __restrict__ bn2bg,
    const float* __restrict__ bn2bv,
    int n, int nb_data)
{
    const int tid = threadIdx.x;
    if (blockIdx.x >= nb_data) {
        const int sb = blockIdx.x - nb_data;
        if (sb < 16) {
            const int id = sb * 256 + tid;
            const int o = id & 15;
            const int pr = id >> 4;
            const int jj = pr & 15;
            const int i = pr >> 4;
            float v;
            if (i < jj)       v = blW[o * 256 + i * 16 + jj] + blW[o * 256 + jj * 16 + i];
            else if (i == jj) v = blW[o * 256 + i * 16 + i];
            else              v = 0.f;
            g_wcat[id] = v;
        } else {
            __shared__ float sM[48], s0[16];
            __shared__ float sca[64], sha[64];
            if (tid < 48) {
                const int r = tid >> 4, u = tid & 15;
                sM[tid] = lp2w[r * 64 + u] + lp2w[r * 64 + 16 + u] +
                          lp2w[r * 64 + 32 + u] + lp2w[r * 64 + 48 + u];
            }
            if (tid >= 48 && tid < 64) {
                const int u = tid - 48;
                s0[u] = lp2b[u] + lp2b[16 + u] + lp2b[32 + u] + lp2b[48 + u];
            }
            if (tid >= 64 && tid < 128) {
                const int c = tid - 64;
                float sc = bn2ag[c] * rsqrtf(bn2av[c] + 1e-5f);
                sca[c] = sc;
                sha[c] = bn2ab[c] - bn2am[c] * sc;
            }
            __syncthreads();
            if (tid < 192) {
                const int r = tid >> 6, c = tid & 63;
                float acc = 0.f;
#pragma unroll
                for (int u = 0; u < 16; u++)
                    acc += sM[r * 16 + u] * c2aw[(16 + u) * 64 + c];
                g_c2aQ[r * 64 + c] = acc * sca[c];
            } else {
                const int c = tid - 192;
                float acc = 0.f;
#pragma unroll
                for (int u = 0; u < 16; u++)
                    acc += s0[u] * c2aw[(16 + u) * 64 + c];
                g_c2aC[c] = acc * sca[c] + sha[c];
            }
#pragma unroll
            for (int t = 0; t < 4; t++) {
                const int i = tid + t * 256;
                g_wcat[4096 + i] = c2aw[i] * sca[i & 63];
            }
#pragma unroll
            for (int t = 0; t < 2; t++) {
                const int i = tid + t * 256;
                const int u = i & 7;
                g_c2bF[i] = c2bw[i] * (bn2bg[u] * rsqrtf(bn2bv[u] + 1e-5f));
            }
        }
        return;
    }

    __shared__ float sw[4096];
    __shared__ float sw1[1024];
    __shared__ float sx[32][64];
    for (int i = tid; i < 1024; i += 256)
        ((float4*)sw)[i] = ((const float4*)w03)[i];
    for (int i = tid; i < 256; i += 256)
        ((float4*)sw1)[i] = ((const float4*)(w01 + 48))[i];
    const int base = blockIdx.x * 32;
    {
        const int c4 = tid & 15;
        const int r = tid >> 4;
#pragma unroll
        for (int a = 0; a < 2; a++) {
            const int row = base + r + a * 16;
            float4 v = make_float4(0.f, 0.f, 0.f, 0.f);
            if (row < n) v = ((const float4*)(x + (size_t)row * 64))[c4];
            ((float4*)sx[r + a * 16])[c4] = v;
        }
    }
    __syncthreads();

    {
        const int rq = tid >> 5;
        const int cp = tid & 31;
        const ull bcp = ((const ull*)b03)[cp];
        ull acc0 = bcp, acc1 = bcp, acc2 = bcp, acc3 = bcp;
#pragma unroll 8
        for (int d = 0; d < 64; d++) {
            const ull w2 = ((const ull*)(sw + d * 64))[cp];
            acc0 = fma2_(bc2(sx[rq * 4 + 0][d]), w2, acc0);
            acc1 = fma2_(bc2(sx[rq * 4 + 1][d]), w2, acc1);
            acc2 = fma2_(bc2(sx[rq * 4 + 2][d]), w2, acc2);
            acc3 = fma2_(bc2(sx[rq * 4 + 3][d]), w2, acc3);
        }
        const int r0 = base + rq * 4;
        if (r0 + 0 < n) ((ull*)(g_y + (size_t)(r0 + 0) * 64))[cp] = acc0;
        if (r0 + 1 < n) ((ull*)(g_y + (size_t)(r0 + 1) * 64))[cp] = acc1;
        if (r0 + 2 < n) ((ull*)(g_y + (size_t)(r0 + 2) * 64))[cp] = acc2;
        if (r0 + 3 < n) ((ull*)(g_y + (size_t)(r0 + 3) * 64))[cp] = acc3;
    }
    {
        const int r = tid >> 3;
        const int o8 = tid & 7;
        ull acc = ((const ull*)b01)[o8];
#pragma unroll 8
        for (int d = 0; d < 64; d++)
            acc = fma2_(bc2(sx[r][d]), ((const ull*)(sw1 + d * 16))[o8], acc);
        const int row = base + r;
        if (row < n) ((ull*)(g_hx + (size_t)row * 16))[o8] = acc;
    }
}

// ---------------------------------------------------------------------------
// Main kernel: 256 threads, 32 points/block, two-phase.
// Phase 1 per-warp covers points 4w..4w+3; __syncwarp between phases.
// Phase 2: half-warp = point, lane = 4-channel group (128-bit ld/st).
// ---------------------------------------------------------------------------
__global__ void __launch_bounds__(256, 2) pm_main_kernel(
    const float* __restrict__ p,
    const int* __restrict__ knn,
    const float* __restrict__ w01, const float* __restrict__ blB,
    const float* __restrict__ lp1w, const float* __restrict__ lp1b,
    const float* __restrict__ bnpg, const float* __restrict__ bnpb,
    const float* __restrict__ bnpm, const float* __restrict__ bnpv,
    const float* __restrict__ lp2w, const float* __restrict__ lp2b,
    const float* __restrict__ bn2bg, const float* __restrict__ bn2bb,
    const float* __restrict__ bn2bm, const float* __restrict__ bn2bv,
    const float* __restrict__ c2cw, const float* __restrict__ c2cb,
    float* __restrict__ out, float* __restrict__ xk_out,
    float* __restrict__ knn_out, float* __restrict__ pr_out,
    int n)
{
    __shared__ __align__(16) float s_ws[512 * 8];   // softmax weights per pair
    __shared__ __align__(16) float s_q[512 * 4];    // q vec per pair
    __shared__ int   s_j[512];                      // gather index per pair
    __shared__ __align__(16) float s_c2aQ[192];
    __shared__ __align__(16) float s_c2aC[64];
    __shared__ __align__(16) float s_c2b[512];
    __shared__ __align__(16) float s_c2c[64];
    __shared__ __align__(16) float s_lp2[192], s_lp2b[64];
    __shared__ __align__(16) float s_w01p[48];
    __shared__ __align__(16) float s_blB[16];
    __shared__ __align__(16) float s_lp1f[12], s_lp1c[4];
    __shared__ __align__(16) float s_bn2bt[8], s_c2cb[8];

    const int tid = threadIdx.x;

    // ---- staging (small tables only) ----
    if (tid < 128) ((float4*)s_c2b)[tid] = ((const float4*)g_c2bF)[tid];
    if (tid < 192) { s_c2aQ[tid] = g_c2aQ[tid]; s_lp2[tid] = lp2w[tid]; }
    if (tid < 64) {
        s_c2aC[tid] = g_c2aC[tid];
        s_lp2b[tid] = lp2b[tid];
        s_c2c[tid] = c2cw[tid];
    }
    if (tid < 48) s_w01p[tid] = w01[tid];
    if (tid < 16) s_blB[tid] = blB[tid];
    if (tid < 8) {
        float sc = bn2bg[tid] * rsqrtf(bn2bv[tid] + 1e-5f);
        s_bn2bt[tid] = bn2bb[tid] - bn2bm[tid] * sc;
        s_c2cb[tid] = c2cb[tid];
    }
    if (tid < 3) {
        const int d = tid;
        float sc = bnpg[d] * rsqrtf(bnpv[d] + 1e-5f);
        s_lp1f[0 + d] = lp1w[0 * 3 + d] * sc;
        s_lp1f[4 + d] = lp1w[1 * 3 + d] * sc;
        s_lp1f[8 + d] = lp1w[2 * 3 + d] * sc;
        s_lp1c[d] = (lp1b[d] - bnpm[d]) * sc + bnpb[d];
    }
    __syncthreads();

    // ---- pair setup ----
    const int k = tid & 15;
    const int half = (tid >> 4) & 1;
    const int wrp = tid >> 5;
    const int pt0 = wrp * 4 + half * 2;             // point within block
    const int base = blockIdx.x * 32 + pt0;
    const int nn0 = base, nn1 = base + 1;
    const bool v0 = nn0 < n, v1 = nn1 < n;
    const int nc0 = v0 ? nn0 : (n > 0 ? n - 1 : 0);
    const int nc1 = v1 ? nn1 : (n > 0 ? n - 1 : 0);
    const int j0 = knn[(size_t)nc0 * 16 + k];
    const int j1 = knn[(size_t)nc1 * 16 + k];

    const float pA0 = p[(size_t)j0 * 3 + 0] - p[(size_t)nc0 * 3 + 0];
    const float pA1 = p[(size_t)j0 * 3 + 1] - p[(size_t)nc0 * 3 + 1];
    const float pA2 = p[(size_t)j0 * 3 + 2] - p[(size_t)nc0 * 3 + 2];
    const float pB0 = p[(size_t)j1 * 3 + 0] - p[(size_t)nc1 * 3 + 0];
    const float pB1 = p[(size_t)j1 * 3 + 1] - p[(size_t)nc1 * 3 + 1];
    const float pB2 = p[(size_t)j1 * 3 + 2] - p[(size_t)nc1 * 3 + 2];
    if (v0 && pr_out) {
        pr_out[((size_t)nn0 * 16 + k) * 3 + 0] = pA0;
        pr_out[((size_t)nn0 * 16 + k) * 3 + 1] = pA1;
        pr_out[((size_t)nn0 * 16 + k) * 3 + 2] = pA2;
    }
    if (v1 && pr_out) {
        pr_out[((size_t)nn1 * 16 + k) * 3 + 0] = pB0;
        pr_out[((size_t)nn1 * 16 + k) * 3 + 1] = pB1;
        pr_out[((size_t)nn1 * 16 + k) * 3 + 2] = pB2;
    }
    if (v0 && knn_out) knn_out[(size_t)nn0 * 16 + k] = (float)j0;
    if (v1 && knn_out) knn_out[(size_t)nn1 * 16 + k] = (float)j1;

    // ---- h = relu(hx[j] + pr @ w01p) ----
    float h0[16], h1[16];
    {
        const float4* hxa = (const float4*)(g_hx + (size_t)j0 * 16);
        const float4* hxb = (const float4*)(g_hx + (size_t)j1 * 16);
#pragma unroll
        for (int o4 = 0; o4 < 4; o4++) {
            float4 a = hxa[o4], b = hxb[o4];
            float4 w0 = *(const float4*)(s_w01p + o4 * 4);
            float4 w1 = *(const float4*)(s_w01p + 16 + o4 * 4);
            float4 w2 = *(const float4*)(s_w01p + 32 + o4 * 4);
            h0[o4 * 4 + 0] = fmaxf(a.x + pA0 * w0.x + pA1 * w1.x + pA2 * w2.x, 0.f);
            h0[o4 * 4 + 1] = fmaxf(a.y + pA0 * w0.y + pA1 * w1.y + pA2 * w2.y, 0.f);
            h0[o4 * 4 + 2] = fmaxf(a.z + pA0 * w0.z + pA1 * w1.z + pA2 * w2.z, 0.f);
            h0[o4 * 4 + 3] = fmaxf(a.w + pA0 * w0.w + pA1 * w1.w + pA2 * w2.w, 0.f);
            h1[o4 * 4 + 0] = fmaxf(b.x + pB0 * w0.x + pB1 * w1.x + pB2 * w2.x, 0.f);
            h1[o4 * 4 + 1] = fmaxf(b.y + pB0 * w0.y + pB1 * w1.y + pB2 * w2.y, 0.f);
            h1[o4 * 4 + 2] = fmaxf(b.z + pB0 * w0.z + pB1 * w1.z + pB2 * w2.z, 0.f);
            h1[o4 * 4 + 3] = fmaxf(b.w + pB0 * w0.w + pB1 * w1.w + pB2 * w2.w, 0.f);
        }
    }

    // ---- symmetrized bilinear, weights from __constant__ ----
    ull e0p[8], e1p[8];
    {
        const ull* bB = (const ull*)s_blB;
#pragma unroll
        for (int q = 0; q < 8; q++) { ull b = bB[q]; e0p[q] = b; e1p[q] = b; }
    }
#pragma unroll
    for (int i = 0; i < 16; i++) {
#pragma unroll
        for (int jj = i; jj < 16; jj++) {
            const ull ga2 = bc2(h0[i] * h0[jj]);
            const ull gb2 = bc2(h1[i] * h1[jj]);
            const ulonglong2* wr = (const ulonglong2*)(c_w + (i * 16 + jj) * 16);
            ulonglong2 w0 = wr[0], w1 = wr[1], w2 = wr[2], w3 = wr[3];
            e0p[0] = fma2_(ga2, w0.x, e0p[0]); e1p[0] = fma2_(gb2, w0.x, e1p[0]);
            e0p[1] = fma2_(ga2, w0.y, e0p[1]); e1p[1] = fma2_(gb2, w0.y, e1p[1]);
            e0p[2] = fma2_(ga2, w1.x, e0p[2]); e1p[2] = fma2_(gb2, w1.x, e1p[2]);
            e0p[3] = fma2_(ga2, w1.y, e0p[3]); e1p[3] = fma2_(gb2, w1.y, e1p[3]);
            e0p[4] = fma2_(ga2, w2.x, e0p[4]); e1p[4] = fma2_(gb2, w2.x, e1p[4]);
            e0p[5] = fma2_(ga2, w2.y, e0p[5]); e1p[5] = fma2_(gb2, w2.y, e1p[5]);
            e0p[6] = fma2_(ga2, w3.x, e0p[6]); e1p[6] = fma2_(gb2, w3.x, e1p[6]);
            e0p[7] = fma2_(ga2, w3.y, e0p[7]); e1p[7] = fma2_(gb2, w3.y, e1p[7]);
        }
    }

    // ---- q vec ----
    float qa[3], qb[3];
#pragma unroll
    for (int d = 0; d < 3; d++) {
        qa[d] = fmaxf(fmaf(pA0, s_lp1f[d], fmaf(pA1, s_lp1f[4 + d], fmaf(pA2, s_lp1f[8 + d], s_lp1c[d]))), 0.f);
        qb[d] = fmaxf(fmaf(pB0, s_lp1f[d], fmaf(pB1, s_lp1f[4 + d], fmaf(pB2, s_lp1f[8 + d], s_lp1c[d]))), 0.f);
    }

    // ---- fused c2a(+q, BN folded)+relu+c2b(BN-scale folded) ----
    ull hb0p[4], hb1p[4];
    {
        const ull* shb = (const ull*)s_bn2bt;
#pragma unroll
        for (int m = 0; m < 4; m++) { ull b = shb[m]; hb0p[m] = b; hb1p[m] = b; }
    }
#pragma unroll
    for (int cb = 0; cb < 4; cb++) {
        ull a0p[8], a1p[8];
        {
            const ulonglong2* ccp = (const ulonglong2*)(s_c2aC + cb * 16);
            ulonglong2 c0 = ccp[0], c1 = ccp[1], c2 = ccp[2], c3 = ccp[3];
            a0p[0] = c0.x; a0p[1] = c0.y; a0p[2] = c1.x; a0p[3] = c1.y;
            a0p[4] = c2.x; a0p[5] = c2.y; a0p[6] = c3.x; a0p[7] = c3.y;
#pragma unroll
            for (int q = 0; q < 8; q++) a1p[q] = a0p[q];
        }
#pragma unroll
        for (int q8 = 0; q8 < 8; q8++) {
            float e0lo, e0hi, e1lo, e1hi;
            upk2(e0p[q8], e0lo, e0hi);
            upk2(e1p[q8], e1lo, e1hi);
#pragma unroll
            for (int hh = 0; hh < 2; hh++) {
                const ull va2 = bc2(hh ? e0hi : e0lo);
                const ull vb2 = bc2(hh ? e1hi : e1lo);
                const ulonglong2* wr = (const ulonglong2*)(c_w + 4096 + (2 * q8 + hh) * 64 + cb * 16);
                ulonglong2 w0 = wr[0], w1 = wr[1], w2 = wr[2], w3 = wr[3];
                a0p[0] = fma2_(va2, w0.x, a0p[0]); a1p[0] = fma2_(vb2, w0.x, a1p[0]);
                a0p[1] = fma2_(va2, w0.y, a0p[1]); a1p[1] = fma2_(vb2, w0.y, a1p[1]);
                a0p[2] = fma2_(va2, w1.x, a0p[2]); a1p[2] = fma2_(vb2, w1.x, a1p[2]);
                a0p[3] = fma2_(va2, w1.y, a0p[3]); a1p[3] = fma2_(vb2, w1.y, a1p[3]);
                a0p[4] = fma2_(va2, w2.x, a0p[4]); a1p[4] = fma2_(vb2, w2.x, a1p[4]);
                a0p[5] = fma2_(va2, w2.y, a0p[5]); a1p[5] = fma2_(vb2, w2.y, a1p[5]);
                a0p[6] = fma2_(va2, w3.x, a0p[6]); a1p[6] = fma2_(vb2, w3.x, a1p[6]);
                a0p[7] = fma2_(va2, w3.y, a0p[7]); a1p[7] = fma2_(vb2, w3.y, a1p[7]);
            }
        }
#pragma unroll
        for (int r = 0; r < 3; r++) {
            const ull va2 = bc2(qa[r]);
            const ull vb2 = bc2(qb[r]);
            const ulonglong2* wr = (const ulonglong2*)(s_c2aQ + r * 64 + cb * 16);
            ulonglong2 w0 = wr[0], w1 = wr[1], w2 = wr[2], w3 = wr[3];
            a0p[0] = fma2_(va2, w0.x, a0p[0]); a1p[0] = fma2_(vb2, w0.x, a1p[0]);
            a0p[1] = fma2_(va2, w0.y, a0p[1]); a1p[1] = fma2_(vb2, w0.y, a1p[1]);
            a0p[2] = fma2_(va2, w1.x, a0p[2]); a1p[2] = fma2_(vb2, w1.x, a1p[2]);
            a0p[3] = fma2_(va2, w1.y, a0p[3]); a1p[3] = fma2_(vb2, w1.y, a1p[3]);
            a0p[4] = fma2_(va2, w2.x, a0p[4]); a1p[4] = fma2_(vb2, w2.x, a1p[4]);
            a0p[5] = fma2_(va2, w2.y, a0p[5]); a1p[5] = fma2_(vb2, w2.y, a1p[5]);
            a0p[6] = fma2_(va2, w3.x, a0p[6]); a1p[6] = fma2_(vb2, w3.x, a1p[6]);
            a0p[7] = fma2_(va2, w3.y, a0p[7]); a1p[7] = fma2_(vb2, w3.y, a1p[7]);
        }
        // relu (BN folded) + c2b (scale folded)
#pragma unroll
        for (int q = 0; q < 8; q++) {
            float v00, v01, v10, v11;
            upk2(a0p[q], v00, v01); upk2(a1p[q], v10, v11);
            v00 = fmaxf(v00, 0.f);
            v01 = fmaxf(v01, 0.f);
            v10 = fmaxf(v10, 0.f);
            v11 = fmaxf(v11, 0.f);
            const ulonglong2* wb0 = (const ulonglong2*)(s_c2b + (cb * 16 + 2 * q) * 8);
            const ulonglong2* wb1 = (const ulonglong2*)(s_c2b + (cb * 16 + 2 * q + 1) * 8);
            ulonglong2 u0 = wb0[0], u1 = wb0[1];
            ulonglong2 u2 = wb1[0], u3 = wb1[1];
            const ull va2 = bc2(v00), vA2 = bc2(v01);
            const ull vb2 = bc2(v10), vB2 = bc2(v11);
            hb0p[0] = fma2_(va2, u0.x, hb0p[0]); hb0p[1] = fma2_(va2, u0.y, hb0p[1]);
            hb0p[2] = fma2_(va2, u1.x, hb0p[2]); hb0p[3] = fma2_(va2, u1.y, hb0p[3]);
            hb0p[0] = fma2_(vA2, u2.x, hb0p[0]); hb0p[1] = fma2_(vA2, u2.y, hb0p[1]);
            hb0p[2] = fma2_(vA2, u3.x, hb0p[2]); hb0p[3] = fma2_(vA2, u3.y, hb0p[3]);
            hb1p[0] = fma2_(vb2, u0.x, hb1p[0]); hb1p[1] = fma2_(vb2, u0.y, hb1p[1]);
            hb1p[2] = fma2_(vb2, u1.x, hb1p[2]); hb1p[3] = fma2_(vb2, u1.y, hb1p[3]);
            hb1p[0] = fma2_(vB2, u2.x, hb1p[0]); hb1p[1] = fma2_(vB2, u2.y, hb1p[1]);
            hb1p[2] = fma2_(vB2, u3.x, hb1p[2]); hb1p[3] = fma2_(vB2, u3.y, hb1p[3]);
        }
    }
    float hbs0[8], hbs1[8];
#pragma unroll
    for (int m = 0; m < 4; m++) {
        upk2(hb0p[m], hbs0[2 * m], hbs0[2 * m + 1]);
        upk2(hb1p[m], hbs1[2 * m], hbs1[2 * m + 1]);
    }
#pragma unroll
    for (int u = 0; u < 8; u++) {
        hbs0[u] = fmaxf(hbs0[u], 0.f);
        hbs1[u] = fmaxf(hbs1[u], 0.f);
    }

    // ---- logits (packed) ----
    ull lg0p[4], lg1p[4];
    {
        const ull* cbp = (const ull*)s_c2cb;
#pragma unroll
        for (int m = 0; m < 4; m++) { ull b = cbp[m]; lg0p[m] = b; lg1p[m] = b; }
    }
#pragma unroll
    for (int u = 0; u < 8; u++) {
        const ull h02 = bc2(hbs0[u]);
        const ull h12 = bc2(hbs1[u]);
        const ulonglong2* wr = (const ulonglong2*)(s_c2c + u * 8);
        ulonglong2 w0 = wr[0], w1 = wr[1];
        lg0p[0] = fma2_(h02, w0.x, lg0p[0]); lg1p[0] = fma2_(h12, w0.x, lg1p[0]);
        lg0p[1] = fma2_(h02, w0.y, lg0p[1]); lg1p[1] = fma2_(h12, w0.y, lg1p[1]);
        lg0p[2] = fma2_(h02, w1.x, lg0p[2]); lg1p[2] = fma2_(h12, w1.x, lg1p[2]);
        lg0p[3] = fma2_(h02, w1.y, lg0p[3]); lg1p[3] = fma2_(h12, w1.y, lg1p[3]);
    }

    // ---- softmax over 16 k-lanes (no max pass; |logits| << 1) ----
    float ws0[8], ws1[8];
#pragma unroll
    for (int m = 0; m < 4; m++) {
        float l0, l1;
        upk2(lg0p[m], l0, l1);
        ws0[2 * m] = __expf(l0); ws0[2 * m + 1] = __expf(l1);
        upk2(lg1p[m], l0, l1);
        ws1[2 * m] = __expf(l0); ws1[2 * m + 1] = __expf(l1);
    }
#pragma unroll
    for (int c = 0; c < 8; c++) {
        float s0 = ws0[c], s1 = ws1[c];
#pragma unroll
        for (int d = 8; d > 0; d >>= 1) {
            s0 += __shfl_xor_sync(0xffffffffu, s0, d);
            s1 += __shfl_xor_sync(0xffffffffu, s1, d);
        }
        ws0[c] = __fdividef(ws0[c], s0);
        ws1[c] = __fdividef(ws1[c], s1);
    }

    // ---- write per-pair state to smem (consumed by THIS warp only) ----
    {
        const int pair0 = pt0 * 16 + k;
        const int pair1 = (pt0 + 1) * 16 + k;
        ull* wsp = (ull*)s_ws;
#pragma unroll
        for (int m = 0; m < 4; m++) {
            wsp[pair0 * 4 + m] = pk2(ws0[2 * m], ws0[2 * m + 1]);
            wsp[pair1 * 4 + m] = pk2(ws1[2 * m], ws1[2 * m + 1]);
        }
        s_q[pair0 * 4 + 0] = qa[0]; s_q[pair0 * 4 + 1] = qa[1];
        s_q[pair0 * 4 + 2] = qa[2]; s_q[pair0 * 4 + 3] = 0.f;
        s_q[pair1 * 4 + 0] = qb[0]; s_q[pair1 * 4 + 1] = qb[1];
        s_q[pair1 * 4 + 2] = qb[2]; s_q[pair1 * 4 + 3] = 0.f;
        s_j[pair0] = j0;
        s_j[pair1] = j1;
    }
    __syncwarp();   // producer warp == consumer warp; no block barrier needed

    // ---- phase 2: coalesced epilogue. half-warp = point, lane = 4-channel
    //      group (128-bit ld/st). out accumulated over k in registers. ----
    {
        const int lane = tid & 31;
        const int w = tid >> 5;
        const int hw = lane >> 4;          // which point of the sub-pair
        const int c4 = lane & 15;          // channel group: floats 4c4..4c4+3
        const ulonglong2 l0 = ((const ulonglong2*)s_lp2)[c4];
        const ulonglong2 l1 = ((const ulonglong2*)(s_lp2 + 64))[c4];
        const ulonglong2 l2 = ((const ulonglong2*)(s_lp2 + 128))[c4];
        const ulonglong2 lb = ((const ulonglong2*)s_lp2b)[c4];
        const ull* wsp = (const ull*)s_ws;
        const int m0 = (2 * c4) & 3;
        const int m1 = (2 * c4 + 1) & 3;
#pragma unroll
        for (int pp = 0; pp < 2; pp++) {
            const int pt = w * 4 + pp * 2 + hw;
            const int nn = blockIdx.x * 32 + pt;
            const bool v = nn < n;
            ull accx = 0ull, accy = 0ull;
#pragma unroll
            for (int kk = 0; kk < 16; kk++) {
                const int pair = pt * 16 + kk;
                const int j = s_j[pair];
                float4 qv = *(const float4*)(s_q + pair * 4);
                const ull wsv0 = wsp[pair * 4 + m0];
                const ull wsv1 = wsp[pair * 4 + m1];
                ulonglong2 y = ((const ulonglong2*)(g_y + (size_t)j * 64))[c4];
                ull pe = fma2_(bc2(qv.x), l0.x,
                         fma2_(bc2(qv.y), l1.x,
                         fma2_(bc2(qv.z), l2.x, lb.x)));
                ull xv0 = mul2_(add2_(y.x, pe), wsv0);
                pe = fma2_(bc2(qv.x), l0.y,
                     fma2_(bc2(qv.y), l1.y,
                     fma2_(bc2(qv.z), l2.y, lb.y)));
                ull xv1 = mul2_(add2_(y.y, pe), wsv1);
                if (v && xk_out) {
                    ulonglong2 t; t.x = xv0; t.y = xv1;
                    ((ulonglong2*)(xk_out + ((size_t)nn * 16 + kk) * 64))[c4] = t;
                }
                accx = add2_(accx, xv0);
                accy = add2_(accy, xv1);
            }
            if (v) {
                ulonglong2 t; t.x = accx; t.y = accy;
                ((ulonglong2*)(out + (size_t)nn * 64))[c4] = t;
            }
        }
    }
}

// ---------------------------------------------------------------------------
extern "C" void kernel_launch(void* const* d_in, const int* in_sizes, int n_in,
                              void* d_out, int out_size)
{
    const float* p    = (const float*)d_in[0];
    const float* x    = (const float*)d_in[1];
    const int*   knn  = (const int*)d_in[2];
    const float* w01  = (const float*)d_in[3];
    const float* b01  = (const float*)d_in[4];
    const float* blW  = (const float*)d_in[5];
    const float* blB  = (const float*)d_in[6];
    const float* lp1w = (const float*)d_in[7];
    const float* lp1b = (const float*)d_in[8];
    const float* bnpg = (const float*)d_in[9];
    const float* bnpb = (const float*)d_in[10];
    const float* bnpm = (const float*)d_in[11];
    const float* bnpv = (const float*)d_in[12];
    const float* lp2w = (const float*)d_in[13];
    const float* lp2b = (const float*)d_in[14];
    const float* c2aw = (const float*)d_in[15];
    const float* bn2ag = (const float*)d_in[16];
    const float* bn2ab = (const float*)d_in[17];
    const float* bn2am = (const float*)d_in[18];
    const float* bn2av = (const float*)d_in[19];
    const float* c2bw  = (const float*)d_in[20];
    const float* bn2bg = (const float*)d_in[21];
    const float* bn2bb = (const float*)d_in[22];
    const float* bn2bm = (const float*)d_in[23];
    const float* bn2bv = (const float*)d_in[24];
    const float* c2cw  = (const float*)d_in[25];
    const float* c2cb  = (const float*)d_in[26];
    const float* w03   = (const float*)d_in[27];
    const float* b03   = (const float*)d_in[28];

    const int n = in_sizes[0] / 3;
    float* out = (float*)d_out;

    const long long total = (long long)n * 64 + (long long)n * 16 * 64 +
                            (long long)n * 16 + (long long)n * 16 * 3;
    float* xk_out = nullptr;
    float* knn_out = nullptr;
    float* pr_out = nullptr;
    if ((long long)out_size >= total) {
        xk_out  = out + (size_t)n * 64;
        knn_out = xk_out + (size_t)n * 16 * 64;
        pr_out  = knn_out + (size_t)n * 16;
    }

    const int nb_data = (n + 31) / 32;
    prep_kernel<<<nb_data + 17, 256>>>(x, w03, b03, w01, b01,
                                       blW, c2aw, lp2w, lp2b,
                                       bn2ag, bn2ab, bn2am, bn2av,
                                       c2bw, bn2bg, bn2bv, n, nb_data);
    // Stage computed weight tables into __constant__ (single D2D memcpy node).
    float* d_wcat = nullptr; cudaGetSymbolAddress((void**)&d_wcat, g_wcat);
    cudaMemcpyToSymbolAsync(c_w, d_wcat, 5120 * sizeof(float), 0,
                            cudaMemcpyDeviceToDevice, 0);
    pm_main_kernel<<<(n + 31) / 32, 256>>>(p, knn, w01, blB,
                               lp1w, lp1b, bnpg, bnpb, bnpm, bnpv, lp2w, lp2b,
                               bn2bg, bn2bb, bn2bm, bn2bv,
                               c2cw, c2cb,
                               out, xk_out, knn_out, pr_out, n);
}

// round 16
// speedup vs baseline: 3.4517x; 1.0058x over previous
#include <cuda_runtime.h>
#include <cstdint>

#define MAXN 100352

typedef unsigned long long ull;

__device__ float g_y[MAXN * 64];   // x @ w03 + b03
__device__ float g_hx[MAXN * 16];  // x @ w01[3:] + b01
__device__ float g_wcat[5120];     // [0:4096)=blS symmetrized, [4096:5120)=c2aF
__device__ float g_c2aQ[192];      // folded q->c2a, BN2a-scale folded
__device__ float g_c2aC[64];       // folded const->c2a, BN2a scale+shift folded
__device__ float g_c2bF[512];      // c2b, BN2b-scale folded

// Uniform weights on the constant port (off the smem crossbar).
__constant__ float c_w[5120];      // [0:4096)=blS, [4096:5120)=c2a

// ---- packed f32x2 helpers (FFMA2) ----
__device__ __forceinline__ ull pk2(float lo, float hi) {
    ull r; asm("mov.b64 %0,{%1,%2};" : "=l"(r) : "f"(lo), "f"(hi)); return r;
}
__device__ __forceinline__ ull bc2(float v) { return pk2(v, v); }
__device__ __forceinline__ void upk2(ull v, float& lo, float& hi) {
    asm("mov.b64 {%0,%1},%2;" : "=f"(lo), "=f"(hi) : "l"(v));
}
__device__ __forceinline__ ull fma2_(ull a, ull b, ull c) {
    ull d; asm("fma.rn.f32x2 %0,%1,%2,%3;" : "=l"(d) : "l"(a), "l"(b), "l"(c)); return d;
}
__device__ __forceinline__ ull add2_(ull a, ull b) {
    ull d; asm("add.rn.f32x2 %0,%1,%2;" : "=l"(d) : "l"(a), "l"(b)); return d;
}
__device__ __forceinline__ ull mul2_(ull a, ull b) {
    ull d; asm("mul.rn.f32x2 %0,%1,%2;" : "=l"(d) : "l"(a), "l"(b)); return d;
}

// ---------------------------------------------------------------------------
// Prep kernel: data blocks compute y & hx (float4 activation reads);
// 17 tail blocks do weight setup.
// ---------------------------------------------------------------------------
__global__ void __launch_bounds__(256) prep_kernel(
    const float* __restrict__ x, const float* __restrict__ w03,
    const float* __restrict__ b03, const float* __restrict__ w01,
    const float* __restrict__ b01,
    const float* __restrict__ blW, const float* __restrict__ c2aw,
    const float* __restrict__ lp2w, const float* __restrict__ lp2b,
    const float* __restrict__ bn2ag, const float* __restrict__ bn2ab,
    const float* __restrict__ bn2am, const float* __restrict__ bn2av,
    const float* __restrict__ c2bw, const float* __restrict__ bn2bg,
    const float* __restrict__ bn2bv,
    int n, int nb_data)
{
    const int tid = threadIdx.x;
    if (blockIdx.x >= nb_data) {
        const int sb = blockIdx.x - nb_data;
        if (sb < 16) {
            const int id = sb * 256 + tid;
            const int o = id & 15;
            const int pr = id >> 4;
            const int jj = pr & 15;
            const int i = pr >> 4;
            float v;
            if (i < jj)       v = blW[o * 256 + i * 16 + jj] + blW[o * 256 + jj * 16 + i];
            else if (i == jj) v = blW[o * 256 + i * 16 + i];
            else              v = 0.f;
            g_wcat[id] = v;
        } else {
            __shared__ float sM[48], s0[16];
            __shared__ float sca[64], sha[64];
            if (tid < 48) {
                const int r = tid >> 4, u = tid & 15;
                sM[tid] = lp2w[r * 64 + u] + lp2w[r * 64 + 16 + u] +
                          lp2w[r * 64 + 32 + u] + lp2w[r * 64 + 48 + u];
            }
            if (tid >= 48 && tid < 64) {
                const int u = tid - 48;
                s0[u] = lp2b[u] + lp2b[16 + u] + lp2b[32 + u] + lp2b[48 + u];
            }
            if (tid >= 64 && tid < 128) {
                const int c = tid - 64;
                float sc = bn2ag[c] * rsqrtf(bn2av[c] + 1e-5f);
                sca[c] = sc;
                sha[c] = bn2ab[c] - bn2am[c] * sc;
            }
            __syncthreads();
            if (tid < 192) {
                const int r = tid >> 6, c = tid & 63;
                float acc = 0.f;
#pragma unroll
                for (int u = 0; u < 16; u++)
                    acc += sM[r * 16 + u] * c2aw[(16 + u) * 64 + c];
                g_c2aQ[r * 64 + c] = acc * sca[c];
            } else {
                const int c = tid - 192;
                float acc = 0.f;
#pragma unroll
                for (int u = 0; u < 16; u++)
                    acc += s0[u] * c2aw[(16 + u) * 64 + c];
                g_c2aC[c] = acc * sca[c] + sha[c];
            }
#pragma unroll
            for (int t = 0; t < 4; t++) {
                const int i = tid + t * 256;
                g_wcat[4096 + i] = c2aw[i] * sca[i & 63];
            }
#pragma unroll
            for (int t = 0; t < 2; t++) {
                const int i = tid + t * 256;
                const int u = i & 7;
                g_c2bF[i] = c2bw[i] * (bn2bg[u] * rsqrtf(bn2bv[u] + 1e-5f));
            }
        }
        return;
    }

    __shared__ float sw[4096];
    __shared__ float sw1[1024];
    __shared__ float sx[32][64];
    for (int i = tid; i < 1024; i += 256)
        ((float4*)sw)[i] = ((const float4*)w03)[i];
    for (int i = tid; i < 256; i += 256)
        ((float4*)sw1)[i] = ((const float4*)(w01 + 48))[i];
    const int base = blockIdx.x * 32;
    {
        const int c4 = tid & 15;
        const int r = tid >> 4;
#pragma unroll
        for (int a = 0; a < 2; a++) {
            const int row = base + r + a * 16;
            float4 v = make_float4(0.f, 0.f, 0.f, 0.f);
            if (row < n) v = ((const float4*)(x + (size_t)row * 64))[c4];
            ((float4*)sx[r + a * 16])[c4] = v;
        }
    }
    __syncthreads();

    // y: warp rq handles rows rq*4..rq*4+3; lane cp -> channels 2cp,2cp+1.
    // Activations read as float4 (LDS.128), weights as warp-uniform LDS.64.
    {
        const int rq = tid >> 5;
        const int cp = tid & 31;
        const ull bcp = ((const ull*)b03)[cp];
        ull acc0 = bcp, acc1 = bcp, acc2 = bcp, acc3 = bcp;
        const ull* swu = (const ull*)sw;
#pragma unroll 4
        for (int d4 = 0; d4 < 16; d4++) {
            float4 x0 = ((const float4*)sx[rq * 4 + 0])[d4];
            float4 x1 = ((const float4*)sx[rq * 4 + 1])[d4];
            float4 x2 = ((const float4*)sx[rq * 4 + 2])[d4];
            float4 x3 = ((const float4*)sx[rq * 4 + 3])[d4];
            const ull w0 = swu[(d4 * 4 + 0) * 32 + cp];
            const ull w1 = swu[(d4 * 4 + 1) * 32 + cp];
            const ull w2 = swu[(d4 * 4 + 2) * 32 + cp];
            const ull w3 = swu[(d4 * 4 + 3) * 32 + cp];
            acc0 = fma2_(bc2(x0.x), w0, acc0); acc0 = fma2_(bc2(x0.y), w1, acc0);
            acc0 = fma2_(bc2(x0.z), w2, acc0); acc0 = fma2_(bc2(x0.w), w3, acc0);
            acc1 = fma2_(bc2(x1.x), w0, acc1); acc1 = fma2_(bc2(x1.y), w1, acc1);
            acc1 = fma2_(bc2(x1.z), w2, acc1); acc1 = fma2_(bc2(x1.w), w3, acc1);
            acc2 = fma2_(bc2(x2.x), w0, acc2); acc2 = fma2_(bc2(x2.y), w1, acc2);
            acc2 = fma2_(bc2(x2.z), w2, acc2); acc2 = fma2_(bc2(x2.w), w3, acc2);
            acc3 = fma2_(bc2(x3.x), w0, acc3); acc3 = fma2_(bc2(x3.y), w1, acc3);
            acc3 = fma2_(bc2(x3.z), w2, acc3); acc3 = fma2_(bc2(x3.w), w3, acc3);
        }
        const int r0 = base + rq * 4;
        if (r0 + 0 < n) ((ull*)(g_y + (size_t)(r0 + 0) * 64))[cp] = acc0;
        if (r0 + 1 < n) ((ull*)(g_y + (size_t)(r0 + 1) * 64))[cp] = acc1;
        if (r0 + 2 < n) ((ull*)(g_y + (size_t)(r0 + 2) * 64))[cp] = acc2;
        if (r0 + 3 < n) ((ull*)(g_y + (size_t)(r0 + 3) * 64))[cp] = acc3;
    }
    // hx: thread row = tid>>3, channels 2o8,2o8+1; float4 activation reads.
    {
        const int r = tid >> 3;
        const int o8 = tid & 7;
        ull acc = ((const ull*)b01)[o8];
        const ull* sw1u = (const ull*)sw1;
#pragma unroll 4
        for (int d4 = 0; d4 < 16; d4++) {
            float4 xv = ((const float4*)sx[r])[d4];
            acc = fma2_(bc2(xv.x), sw1u[(d4 * 4 + 0) * 8 + o8], acc);
            acc = fma2_(bc2(xv.y), sw1u[(d4 * 4 + 1) * 8 + o8], acc);
            acc = fma2_(bc2(xv.z), sw1u[(d4 * 4 + 2) * 8 + o8], acc);
            acc = fma2_(bc2(xv.w), sw1u[(d4 * 4 + 3) * 8 + o8], acc);
        }
        const int row = base + r;
        if (row < n) ((ull*)(g_hx + (size_t)row * 16))[o8] = acc;
    }
}

// ---------------------------------------------------------------------------
// Main kernel: 256 threads, 32 points/block, two-phase (R15 golden).
// Phase 1 per-warp covers points 4w..4w+3; __syncwarp between phases.
// Phase 2: half-warp = point, lane = 4-channel group (128-bit ld/st).
// ---------------------------------------------------------------------------
__global__ void __launch_bounds__(256, 2) pm_main_kernel(
    const float* __restrict__ p,
    const int* __restrict__ knn,
    const float* __restrict__ w01, const float* __restrict__ blB,
    const float* __restrict__ lp1w, const float* __restrict__ lp1b,
    const float* __restrict__ bnpg, const float* __restrict__ bnpb,
    const float* __restrict__ bnpm, const float* __restrict__ bnpv,
    const float* __restrict__ lp2w, const float* __restrict__ lp2b,
    const float* __restrict__ bn2bg, const float* __restrict__ bn2bb,
    const float* __restrict__ bn2bm, const float* __restrict__ bn2bv,
    const float* __restrict__ c2cw, const float* __restrict__ c2cb,
    float* __restrict__ out, float* __restrict__ xk_out,
    float* __restrict__ knn_out, float* __restrict__ pr_out,
    int n)
{
    __shared__ __align__(16) float s_ws[512 * 8];   // softmax weights per pair
    __shared__ __align__(16) float s_q[512 * 4];    // q vec per pair
    __shared__ int   s_j[512];                      // gather index per pair
    __shared__ __align__(16) float s_c2aQ[192];
    __shared__ __align__(16) float s_c2aC[64];
    __shared__ __align__(16) float s_c2b[512];
    __shared__ __align__(16) float s_c2c[64];
    __shared__ __align__(16) float s_lp2[192], s_lp2b[64];
    __shared__ __align__(16) float s_w01p[48];
    __shared__ __align__(16) float s_blB[16];
    __shared__ __align__(16) float s_lp1f[12], s_lp1c[4];
    __shared__ __align__(16) float s_bn2bt[8], s_c2cb[8];

    const int tid = threadIdx.x;

    // ---- staging (small tables only) ----
    if (tid < 128) ((float4*)s_c2b)[tid] = ((const float4*)g_c2bF)[tid];
    if (tid < 192) { s_c2aQ[tid] = g_c2aQ[tid]; s_lp2[tid] = lp2w[tid]; }
    if (tid < 64) {
        s_c2aC[tid] = g_c2aC[tid];
        s_lp2b[tid] = lp2b[tid];
        s_c2c[tid] = c2cw[tid];
    }
    if (tid < 48) s_w01p[tid] = w01[tid];
    if (tid < 16) s_blB[tid] = blB[tid];
    if (tid < 8) {
        float sc = bn2bg[tid] * rsqrtf(bn2bv[tid] + 1e-5f);
        s_bn2bt[tid] = bn2bb[tid] - bn2bm[tid] * sc;
        s_c2cb[tid] = c2cb[tid];
    }
    if (tid < 3) {
        const int d = tid;
        float sc = bnpg[d] * rsqrtf(bnpv[d] + 1e-5f);
        s_lp1f[0 + d] = lp1w[0 * 3 + d] * sc;
        s_lp1f[4 + d] = lp1w[1 * 3 + d] * sc;
        s_lp1f[8 + d] = lp1w[2 * 3 + d] * sc;
        s_lp1c[d] = (lp1b[d] - bnpm[d]) * sc + bnpb[d];
    }
    __syncthreads();

    // ---- pair setup ----
    const int k = tid & 15;
    const int half = (tid >> 4) & 1;
    const int wrp = tid >> 5;
    const int pt0 = wrp * 4 + half * 2;             // point within block
    const int base = blockIdx.x * 32 + pt0;
    const int nn0 = base, nn1 = base + 1;
    const bool v0 = nn0 < n, v1 = nn1 < n;
    const int nc0 = v0 ? nn0 : (n > 0 ? n - 1 : 0);
    const int nc1 = v1 ? nn1 : (n > 0 ? n - 1 : 0);
    const int j0 = knn[(size_t)nc0 * 16 + k];
    const int j1 = knn[(size_t)nc1 * 16 + k];

    const float pA0 = p[(size_t)j0 * 3 + 0] - p[(size_t)nc0 * 3 + 0];
    const float pA1 = p[(size_t)j0 * 3 + 1] - p[(size_t)nc0 * 3 + 1];
    const float pA2 = p[(size_t)j0 * 3 + 2] - p[(size_t)nc0 * 3 + 2];
    const float pB0 = p[(size_t)j1 * 3 + 0] - p[(size_t)nc1 * 3 + 0];
    const float pB1 = p[(size_t)j1 * 3 + 1] - p[(size_t)nc1 * 3 + 1];
    const float pB2 = p[(size_t)j1 * 3 + 2] - p[(size_t)nc1 * 3 + 2];
    if (v0 && pr_out) {
        pr_out[((size_t)nn0 * 16 + k) * 3 + 0] = pA0;
        pr_out[((size_t)nn0 * 16 + k) * 3 + 1] = pA1;
        pr_out[((size_t)nn0 * 16 + k) * 3 + 2] = pA2;
    }
    if (v1 && pr_out) {
        pr_out[((size_t)nn1 * 16 + k) * 3 + 0] = pB0;
        pr_out[((size_t)nn1 * 16 + k) * 3 + 1] = pB1;
        pr_out[((size_t)nn1 * 16 + k) * 3 + 2] = pB2;
    }
    if (v0 && knn_out) knn_out[(size_t)nn0 * 16 + k] = (float)j0;
    if (v1 && knn_out) knn_out[(size_t)nn1 * 16 + k] = (float)j1;

    // ---- h = relu(hx[j] + pr @ w01p) ----
    float h0[16], h1[16];
    {
        const float4* hxa = (const float4*)(g_hx + (size_t)j0 * 16);
        const float4* hxb = (const float4*)(g_hx + (size_t)j1 * 16);
#pragma unroll
        for (int o4 = 0; o4 < 4; o4++) {
            float4 a = hxa[o4], b = hxb[o4];
            float4 w0 = *(const float4*)(s_w01p + o4 * 4);
            float4 w1 = *(const float4*)(s_w01p + 16 + o4 * 4);
            float4 w2 = *(const float4*)(s_w01p + 32 + o4 * 4);
            h0[o4 * 4 + 0] = fmaxf(a.x + pA0 * w0.x + pA1 * w1.x + pA2 * w2.x, 0.f);
            h0[o4 * 4 + 1] = fmaxf(a.y + pA0 * w0.y + pA1 * w1.y + pA2 * w2.y, 0.f);
            h0[o4 * 4 + 2] = fmaxf(a.z + pA0 * w0.z + pA1 * w1.z + pA2 * w2.z, 0.f);
            h0[o4 * 4 + 3] = fmaxf(a.w + pA0 * w0.w + pA1 * w1.w + pA2 * w2.w, 0.f);
            h1[o4 * 4 + 0] = fmaxf(b.x + pB0 * w0.x + pB1 * w1.x + pB2 * w2.x, 0.f);
            h1[o4 * 4 + 1] = fmaxf(b.y + pB0 * w0.y + pB1 * w1.y + pB2 * w2.y, 0.f);
            h1[o4 * 4 + 2] = fmaxf(b.z + pB0 * w0.z + pB1 * w1.z + pB2 * w2.z, 0.f);
            h1[o4 * 4 + 3] = fmaxf(b.w + pB0 * w0.w + pB1 * w1.w + pB2 * w2.w, 0.f);
        }
    }

    // ---- symmetrized bilinear, weights from __constant__ ----
    ull e0p[8], e1p[8];
    {
        const ull* bB = (const ull*)s_blB;
#pragma unroll
        for (int q = 0; q < 8; q++) { ull b = bB[q]; e0p[q] = b; e1p[q] = b; }
    }
#pragma unroll
    for (int i = 0; i < 16; i++) {
#pragma unroll
        for (int jj = i; jj < 16; jj++) {
            const ull ga2 = bc2(h0[i] * h0[jj]);
            const ull gb2 = bc2(h1[i] * h1[jj]);
            const ulonglong2* wr = (const ulonglong2*)(c_w + (i * 16 + jj) * 16);
            ulonglong2 w0 = wr[0], w1 = wr[1], w2 = wr[2], w3 = wr[3];
            e0p[0] = fma2_(ga2, w0.x, e0p[0]); e1p[0] = fma2_(gb2, w0.x, e1p[0]);
            e0p[1] = fma2_(ga2, w0.y, e0p[1]); e1p[1] = fma2_(gb2, w0.y, e1p[1]);
            e0p[2] = fma2_(ga2, w1.x, e0p[2]); e1p[2] = fma2_(gb2, w1.x, e1p[2]);
            e0p[3] = fma2_(ga2, w1.y, e0p[3]); e1p[3] = fma2_(gb2, w1.y, e1p[3]);
            e0p[4] = fma2_(ga2, w2.x, e0p[4]); e1p[4] = fma2_(gb2, w2.x, e1p[4]);
            e0p[5] = fma2_(ga2, w2.y, e0p[5]); e1p[5] = fma2_(gb2, w2.y, e1p[5]);
            e0p[6] = fma2_(ga2, w3.x, e0p[6]); e1p[6] = fma2_(gb2, w3.x, e1p[6]);
            e0p[7] = fma2_(ga2, w3.y, e0p[7]); e1p[7] = fma2_(gb2, w3.y, e1p[7]);
        }
    }

    // ---- q vec ----
    float qa[3], qb[3];
#pragma unroll
    for (int d = 0; d < 3; d++) {
        qa[d] = fmaxf(fmaf(pA0, s_lp1f[d], fmaf(pA1, s_lp1f[4 + d], fmaf(pA2, s_lp1f[8 + d], s_lp1c[d]))), 0.f);
        qb[d] = fmaxf(fmaf(pB0, s_lp1f[d], fmaf(pB1, s_lp1f[4 + d], fmaf(pB2, s_lp1f[8 + d], s_lp1c[d]))), 0.f);
    }

    // ---- fused c2a(+q, BN folded)+relu+c2b(BN-scale folded) ----
    ull hb0p[4], hb1p[4];
    {
        const ull* shb = (const ull*)s_bn2bt;
#pragma unroll
        for (int m = 0; m < 4; m++) { ull b = shb[m]; hb0p[m] = b; hb1p[m] = b; }
    }
#pragma unroll
    for (int cb = 0; cb < 4; cb++) {
        ull a0p[8], a1p[8];
        {
            const ulonglong2* ccp = (const ulonglong2*)(s_c2aC + cb * 16);
            ulonglong2 c0 = ccp[0], c1 = ccp[1], c2 = ccp[2], c3 = ccp[3];
            a0p[0] = c0.x; a0p[1] = c0.y; a0p[2] = c1.x; a0p[3] = c1.y;
            a0p[4] = c2.x; a0p[5] = c2.y; a0p[6] = c3.x; a0p[7] = c3.y;
#pragma unroll
            for (int q = 0; q < 8; q++) a1p[q] = a0p[q];
        }
#pragma unroll
        for (int q8 = 0; q8 < 8; q8++) {
            float e0lo, e0hi, e1lo, e1hi;
            upk2(e0p[q8], e0lo, e0hi);
            upk2(e1p[q8], e1lo, e1hi);
#pragma unroll
            for (int hh = 0; hh < 2; hh++) {
                const ull va2 = bc2(hh ? e0hi : e0lo);
                const ull vb2 = bc2(hh ? e1hi : e1lo);
                const ulonglong2* wr = (const ulonglong2*)(c_w + 4096 + (2 * q8 + hh) * 64 + cb * 16);
                ulonglong2 w0 = wr[0], w1 = wr[1], w2 = wr[2], w3 = wr[3];
                a0p[0] = fma2_(va2, w0.x, a0p[0]); a1p[0] = fma2_(vb2, w0.x, a1p[0]);
                a0p[1] = fma2_(va2, w0.y, a0p[1]); a1p[1] = fma2_(vb2, w0.y, a1p[1]);
                a0p[2] = fma2_(va2, w1.x, a0p[2]); a1p[2] = fma2_(vb2, w1.x, a1p[2]);
                a0p[3] = fma2_(va2, w1.y, a0p[3]); a1p[3] = fma2_(vb2, w1.y, a1p[3]);
                a0p[4] = fma2_(va2, w2.x, a0p[4]); a1p[4] = fma2_(vb2, w2.x, a1p[4]);
                a0p[5] = fma2_(va2, w2.y, a0p[5]); a1p[5] = fma2_(vb2, w2.y, a1p[5]);
                a0p[6] = fma2_(va2, w3.x, a0p[6]); a1p[6] = fma2_(vb2, w3.x, a1p[6]);
                a0p[7] = fma2_(va2, w3.y, a0p[7]); a1p[7] = fma2_(vb2, w3.y, a1p[7]);
            }
        }
#pragma unroll
        for (int r = 0; r < 3; r++) {
            const ull va2 = bc2(qa[r]);
            const ull vb2 = bc2(qb[r]);
            const ulonglong2* wr = (const ulonglong2*)(s_c2aQ + r * 64 + cb * 16);
            ulonglong2 w0 = wr[0], w1 = wr[1], w2 = wr[2], w3 = wr[3];
            a0p[0] = fma2_(va2, w0.x, a0p[0]); a1p[0] = fma2_(vb2, w0.x, a1p[0]);
            a0p[1] = fma2_(va2, w0.y, a0p[1]); a1p[1] = fma2_(vb2, w0.y, a1p[1]);
            a0p[2] = fma2_(va2, w1.x, a0p[2]); a1p[2] = fma2_(vb2, w1.x, a1p[2]);
            a0p[3] = fma2_(va2, w1.y, a0p[3]); a1p[3] = fma2_(vb2, w1.y, a1p[3]);
            a0p[4] = fma2_(va2, w2.x, a0p[4]); a1p[4] = fma2_(vb2, w2.x, a1p[4]);
            a0p[5] = fma2_(va2, w2.y, a0p[5]); a1p[5] = fma2_(vb2, w2.y, a1p[5]);
            a0p[6] = fma2_(va2, w3.x, a0p[6]); a1p[6] = fma2_(vb2, w3.x, a1p[6]);
            a0p[7] = fma2_(va2, w3.y, a0p[7]); a1p[7] = fma2_(vb2, w3.y, a1p[7]);
        }
        // relu (BN folded) + c2b (scale folded)
#pragma unroll
        for (int q = 0; q < 8; q++) {
            float v00, v01, v10, v11;
            upk2(a0p[q], v00, v01); upk2(a1p[q], v10, v11);
            v00 = fmaxf(v00, 0.f);
            v01 = fmaxf(v01, 0.f);
            v10 = fmaxf(v10, 0.f);
            v11 = fmaxf(v11, 0.f);
            const ulonglong2* wb0 = (const ulonglong2*)(s_c2b + (cb * 16 + 2 * q) * 8);
            const ulonglong2* wb1 = (const ulonglong2*)(s_c2b + (cb * 16 + 2 * q + 1) * 8);
            ulonglong2 u0 = wb0[0], u1 = wb0[1];
            ulonglong2 u2 = wb1[0], u3 = wb1[1];
            const ull va2 = bc2(v00), vA2 = bc2(v01);
            const ull vb2 = bc2(v10), vB2 = bc2(v11);
            hb0p[0] = fma2_(va2, u0.x, hb0p[0]); hb0p[1] = fma2_(va2, u0.y, hb0p[1]);
            hb0p[2] = fma2_(va2, u1.x, hb0p[2]); hb0p[3] = fma2_(va2, u1.y, hb0p[3]);
            hb0p[0] = fma2_(vA2, u2.x, hb0p[0]); hb0p[1] = fma2_(vA2, u2.y, hb0p[1]);
            hb0p[2] = fma2_(vA2, u3.x, hb0p[2]); hb0p[3] = fma2_(vA2, u3.y, hb0p[3]);
            hb1p[0] = fma2_(vb2, u0.x, hb1p[0]); hb1p[1] = fma2_(vb2, u0.y, hb1p[1]);
            hb1p[2] = fma2_(vb2, u1.x, hb1p[2]); hb1p[3] = fma2_(vb2, u1.y, hb1p[3]);
            hb1p[0] = fma2_(vB2, u2.x, hb1p[0]); hb1p[1] = fma2_(vB2, u2.y, hb1p[1]);
            hb1p[2] = fma2_(vB2, u3.x, hb1p[2]); hb1p[3] = fma2_(vB2, u3.y, hb1p[3]);
        }
    }
    float hbs0[8], hbs1[8];
#pragma unroll
    for (int m = 0; m < 4; m++) {
        upk2(hb0p[m], hbs0[2 * m], hbs0[2 * m + 1]);
        upk2(hb1p[m], hbs1[2 * m], hbs1[2 * m + 1]);
    }
#pragma unroll
    for (int u = 0; u < 8; u++) {
        hbs0[u] = fmaxf(hbs0[u], 0.f);
        hbs1[u] = fmaxf(hbs1[u], 0.f);
    }

    // ---- logits (packed) ----
    ull lg0p[4], lg1p[4];
    {
        const ull* cbp = (const ull*)s_c2cb;
#pragma unroll
        for (int m = 0; m < 4; m++) { ull b = cbp[m]; lg0p[m] = b; lg1p[m] = b; }
    }
#pragma unroll
    for (int u = 0; u < 8; u++) {
        const ull h02 = bc2(hbs0[u]);
        const ull h12 = bc2(hbs1[u]);
        const ulonglong2* wr = (const ulonglong2*)(s_c2c + u * 8);
        ulonglong2 w0 = wr[0], w1 = wr[1];
        lg0p[0] = fma2_(h02, w0.x, lg0p[0]); lg1p[0] = fma2_(h12, w0.x, lg1p[0]);
        lg0p[1] = fma2_(h02, w0.y, lg0p[1]); lg1p[1] = fma2_(h12, w0.y, lg1p[1]);
        lg0p[2] = fma2_(h02, w1.x, lg0p[2]); lg1p[2] = fma2_(h12, w1.x, lg1p[2]);
        lg0p[3] = fma2_(h02, w1.y, lg0p[3]); lg1p[3] = fma2_(h12, w1.y, lg1p[3]);
    }

    // ---- softmax over 16 k-lanes (no max pass; |logits| << 1) ----
    float ws0[8], ws1[8];
#pragma unroll
    for (int m = 0; m < 4; m++) {
        float l0, l1;
        upk2(lg0p[m], l0, l1);
        ws0[2 * m] = __expf(l0); ws0[2 * m + 1] = __expf(l1);
        upk2(lg1p[m], l0, l1);
        ws1[2 * m] = __expf(l0); ws1[2 * m + 1] = __expf(l1);
    }
#pragma unroll
    for (int c = 0; c < 8; c++) {
        float s0 = ws0[c], s1 = ws1[c];
#pragma unroll
        for (int d = 8; d > 0; d >>= 1) {
            s0 += __shfl_xor_sync(0xffffffffu, s0, d);
            s1 += __shfl_xor_sync(0xffffffffu, s1, d);
        }
        ws0[c] = __fdividef(ws0[c], s0);
        ws1[c] = __fdividef(ws1[c], s1);
    }

    // ---- write per-pair state to smem (consumed by THIS warp only) ----
    {
        const int pair0 = pt0 * 16 + k;
        const int pair1 = (pt0 + 1) * 16 + k;
        ull* wsp = (ull*)s_ws;
#pragma unroll
        for (int m = 0; m < 4; m++) {
            wsp[pair0 * 4 + m] = pk2(ws0[2 * m], ws0[2 * m + 1]);
            wsp[pair1 * 4 + m] = pk2(ws1[2 * m], ws1[2 * m + 1]);
        }
        s_q[pair0 * 4 + 0] = qa[0]; s_q[pair0 * 4 + 1] = qa[1];
        s_q[pair0 * 4 + 2] = qa[2]; s_q[pair0 * 4 + 3] = 0.f;
        s_q[pair1 * 4 + 0] = qb[0]; s_q[pair1 * 4 + 1] = qb[1];
        s_q[pair1 * 4 + 2] = qb[2]; s_q[pair1 * 4 + 3] = 0.f;
        s_j[pair0] = j0;
        s_j[pair1] = j1;
    }
    __syncwarp();   // producer warp == consumer warp; no block barrier needed

    // ---- phase 2: coalesced epilogue. half-warp = point, lane = 4-channel
    //      group (128-bit ld/st). out accumulated over k in registers. ----
    {
        const int lane = tid & 31;
        const int w = tid >> 5;
        const int hw = lane >> 4;          // which point of the sub-pair
        const int c4 = lane & 15;          // channel group: floats 4c4..4c4+3
        const ulonglong2 l0 = ((const ulonglong2*)s_lp2)[c4];
        const ulonglong2 l1 = ((const ulonglong2*)(s_lp2 + 64))[c4];
        const ulonglong2 l2 = ((const ulonglong2*)(s_lp2 + 128))[c4];
        const ulonglong2 lb = ((const ulonglong2*)s_lp2b)[c4];
        const ull* wsp = (const ull*)s_ws;
        const int m0 = (2 * c4) & 3;
        const int m1 = (2 * c4 + 1) & 3;
#pragma unroll
        for (int pp = 0; pp < 2; pp++) {
            const int pt = w * 4 + pp * 2 + hw;
            const int nn = blockIdx.x * 32 + pt;
            const bool v = nn < n;
            ull accx = 0ull, accy = 0ull;
#pragma unroll
            for (int kk = 0; kk < 16; kk++) {
                const int pair = pt * 16 + kk;
                const int j = s_j[pair];
                float4 qv = *(const float4*)(s_q + pair * 4);
                const ull wsv0 = wsp[pair * 4 + m0];
                const ull wsv1 = wsp[pair * 4 + m1];
                ulonglong2 y = ((const ulonglong2*)(g_y + (size_t)j * 64))[c4];
                ull pe = fma2_(bc2(qv.x), l0.x,
                         fma2_(bc2(qv.y), l1.x,
                         fma2_(bc2(qv.z), l2.x, lb.x)));
                ull xv0 = mul2_(add2_(y.x, pe), wsv0);
                pe = fma2_(bc2(qv.x), l0.y,
                     fma2_(bc2(qv.y), l1.y,
                     fma2_(bc2(qv.z), l2.y, lb.y)));
                ull xv1 = mul2_(add2_(y.y, pe), wsv1);
                if (v && xk_out) {
                    ulonglong2 t; t.x = xv0; t.y = xv1;
                    ((ulonglong2*)(xk_out + ((size_t)nn * 16 + kk) * 64))[c4] = t;
                }
                accx = add2_(accx, xv0);
                accy = add2_(accy, xv1);
            }
            if (v) {
                ulonglong2 t; t.x = accx; t.y = accy;
                ((ulonglong2*)(out + (size_t)nn * 64))[c4] = t;
            }
        }
    }
}

// ---------------------------------------------------------------------------
extern "C" void kernel_launch(void* const* d_in, const int* in_sizes, int n_in,
                              void* d_out, int out_size)
{
    const float* p    = (const float*)d_in[0];
    const float* x    = (const float*)d_in[1];
    const int*   knn  = (const int*)d_in[2];
    const float* w01  = (const float*)d_in[3];
    const float* b01  = (const float*)d_in[4];
    const float* blW  = (const float*)d_in[5];
    const float* blB  = (const float*)d_in[6];
    const float* lp1w = (const float*)d_in[7];
    const float* lp1b = (const float*)d_in[8];
    const float* bnpg = (const float*)d_in[9];
    const float* bnpb = (const float*)d_in[10];
    const float* bnpm = (const float*)d_in[11];
    const float* bnpv = (const float*)d_in[12];
    const float* lp2w = (const float*)d_in[13];
    const float* lp2b = (const float*)d_in[14];
    const float* c2aw = (const float*)d_in[15];
    const float* bn2ag = (const float*)d_in[16];
    const float* bn2ab = (const float*)d_in[17];
    const float* bn2am = (const float*)d_in[18];
    const float* bn2av = (const float*)d_in[19];
    const float* c2bw  = (const float*)d_in[20];
    const float* bn2bg = (const float*)d_in[21];
    const float* bn2bb = (const float*)d_in[22];
    const float* bn2bm = (const float*)d_in[23];
    const float* bn2bv = (const float*)d_in[24];
    const float* c2cw  = (const float*)d_in[25];
    const float* c2cb  = (const float*)d_in[26];
    const float* w03   = (const float*)d_in[27];
    const float* b03   = (const float*)d_in[28];

    const int n = in_sizes[0] / 3;
    float* out = (float*)d_out;

    const long long total = (long long)n * 64 + (long long)n * 16 * 64 +
                            (long long)n * 16 + (long long)n * 16 * 3;
    float* xk_out = nullptr;
    float* knn_out = nullptr;
    float* pr_out = nullptr;
    if ((long long)out_size >= total) {
        xk_out  = out + (size_t)n * 64;
        knn_out = xk_out + (size_t)n * 16 * 64;
        pr_out  = knn_out + (size_t)n * 16;
    }

    const int nb_data = (n + 31) / 32;
    prep_kernel<<<nb_data + 17, 256>>>(x, w03, b03, w01, b01,
                                       blW, c2aw, lp2w, lp2b,
                                       bn2ag, bn2ab, bn2am, bn2av,
                                       c2bw, bn2bg, bn2bv, n, nb_data);
    // Stage computed weight tables into __constant__ (single D2D memcpy node).
    float* d_wcat = nullptr; cudaGetSymbolAddress((void**)&d_wcat, g_wcat);
    cudaMemcpyToSymbolAsync(c_w, d_wcat, 5120 * sizeof(float), 0,
                            cudaMemcpyDeviceToDevice, 0);
    pm_main_kernel<<<(n + 31) / 32, 256>>>(p, knn, w01, blB,
                               lp1w, lp1b, bnpg, bnpb, bnpm, bnpv, lp2w, lp2b,
                               bn2bg, bn2bb, bn2bm, bn2bv,
                               c2cw, c2cb,
                               out, xk_out, knn_out, pr_out, n);
}